// round 9
// baseline (speedup 1.0000x reference)
#include <cuda_runtime.h>
#include <cstdint>

#define N 4096
#define D 128
#define BHALF 2048
#define INV_T 14.285714285714285714f  /* 1/0.07 */

// ---------------- scratch (static device globals; no allocation) ----------------
__device__ __align__(16) float    g_f[N * D];      // L2-normalized features, fp32
__device__ __align__(16) unsigned g_ftf[N * D];    // tf32-rounded copies (bit pattern)
__device__ int    g_cnt[N];
__device__ int    g_sidx[N * 64];
__device__ float  g_sval[N * 64];
__device__ float  g_partial[N * 32];               // [row][slot] coalesced for rowfix
__device__ float  g_lp[N];
__device__ int    g_done;                          // zero-init; reset by last block each call

// ---------------- K1: fused L2-norm (warp 0) + row-wise sparsemax ----------------
#define CAND_MAX 128

__global__ void __launch_bounds__(512) k_sparse(const float* __restrict__ feat,
                                                const float* __restrict__ attn,
                                                float* __restrict__ outm) {
    const int i = blockIdx.x;
    const int tid = threadIdx.x;
    __shared__ __align__(16) float zs[N];          // staging for coalesced stores
    __shared__ float wred[16];
    __shared__ int   wcnt[16];
    __shared__ float s_max, s_tau;
    __shared__ int   s_ccnt, s_fb;
    __shared__ int   s_cidx[CAND_MAX];
    __shared__ float s_cval[CAND_MAX];

    // norm prologue: warp 0 normalizes feature row i, then signals PDL trigger
    if (tid < 32) {
        float4 v = *(const float4*)(feat + (size_t)i * D + tid * 4);
        float s = v.x * v.x + v.y * v.y + v.z * v.z + v.w * v.w;
        #pragma unroll
        for (int o = 16; o; o >>= 1) s += __shfl_xor_sync(0xffffffffu, s, o);
        float r = sqrtf(s);
        float4 f = make_float4(v.x / r, v.y / r, v.z / r, v.w / r);
        *(float4*)(g_f + (size_t)i * D + tid * 4) = f;
        uint4 tf;
        asm("cvt.rna.tf32.f32 %0, %1;" : "=r"(tf.x) : "f"(f.x));
        asm("cvt.rna.tf32.f32 %0, %1;" : "=r"(tf.y) : "f"(f.y));
        asm("cvt.rna.tf32.f32 %0, %1;" : "=r"(tf.z) : "f"(f.z));
        asm("cvt.rna.tf32.f32 %0, %1;" : "=r"(tf.w) : "f"(f.w));
        *(uint4*)(g_ftf + (size_t)i * D + tid * 4) = tf;
        __syncwarp();
        if (tid == 0) {
            __threadfence();
            cudaTriggerProgrammaticLaunchCompletion();   // g_f/g_ftf for row i published
        }
    }

    const int j1 = i & (BHALF - 1);
    const int j2 = j1 + BHALF;
    const float4* row4 = (const float4*)(attn + (size_t)i * N);

    // pass A: vectorized load, scale, mask positives/diag, track max
    float z[8];
    float mx = -3.402823466e38f;
    #pragma unroll
    for (int it = 0; it < 2; it++) {
        int v = tid + it * 512;            // float4 index 0..1023
        float4 r = row4[v];
        int j = v * 4;
        float z0 = (j     == j1 || j     == j2) ? 0.f : r.x * INV_T;
        float z1 = (j + 1 == j1 || j + 1 == j2) ? 0.f : r.y * INV_T;
        float z2 = (j + 2 == j1 || j + 2 == j2) ? 0.f : r.z * INV_T;
        float z3 = (j + 3 == j1 || j + 3 == j2) ? 0.f : r.w * INV_T;
        z[it * 4] = z0; z[it * 4 + 1] = z1; z[it * 4 + 2] = z2; z[it * 4 + 3] = z3;
        mx = fmaxf(mx, fmaxf(fmaxf(z0, z1), fmaxf(z2, z3)));
    }
    #pragma unroll
    for (int o = 16; o; o >>= 1) mx = fmaxf(mx, __shfl_xor_sync(0xffffffffu, mx, o));
    if ((tid & 31) == 0) wred[tid >> 5] = mx;
    if (tid == 0) s_ccnt = 0;
    __syncthreads();
    if (tid == 0) {
        float m = wred[0];
        for (int w = 1; w < 16; w++) m = fmaxf(m, wred[w]);
        s_max = m;
    }
    __syncthreads();

    // pass B: gather candidates z >= max - 1 (sparsemax support bound)
    const float thr = s_max - 1.0f;
    #pragma unroll
    for (int it = 0; it < 2; it++) {
        int j = (tid + it * 512) * 4;
        #pragma unroll
        for (int q = 0; q < 4; q++) {
            float v = z[it * 4 + q];
            if (v >= thr) {
                int p = atomicAdd(&s_ccnt, 1);
                if (p < CAND_MAX) { s_cidx[p] = j + q; s_cval[p] = v; }
            }
        }
    }
    __syncthreads();

    if (tid == 0) {
        int cnt = s_ccnt;
        s_fb = (cnt > CAND_MAX);
        if (!s_fb) {
            // insertion sort desc by (value, index asc) -> deterministic
            for (int a = 1; a < cnt; a++) {
                float v = s_cval[a]; int ix = s_cidx[a];
                int b = a - 1;
                while (b >= 0 && (s_cval[b] < v || (s_cval[b] == v && s_cidx[b] > ix))) {
                    s_cval[b + 1] = s_cval[b]; s_cidx[b + 1] = s_cidx[b]; b--;
                }
                s_cval[b + 1] = v; s_cidx[b + 1] = ix;
            }
            // reference formula: fp32 sequential cumsum over descending values
            float cum = 0.f, cumkz = 1.f; int kz = 1;
            for (int k = 1; k <= cnt; k++) {
                float v = s_cval[k - 1];
                cum += v;
                if (1.0f + (float)k * v > cum) { kz = k; cumkz = cum; }
            }
            float tau = (cumkz - 1.0f) / (float)kz;
            s_tau = tau;
            g_cnt[i] = kz;
            int lim = kz < 64 ? kz : 64;
            for (int k = 0; k < lim; k++) {
                g_sidx[i * 64 + k] = s_cidx[k];
                g_sval[i * 64 + k] = s_cval[k] - tau;
            }
        }
    }
    __syncthreads();

    if (s_fb) {
        // fp32 Michelot fallback (safety only)
        float tau = -3.402823466e38f;
        for (int iter = 0; iter < 64; iter++) {
            float s = 0.f; int c = 0;
            #pragma unroll
            for (int it = 0; it < 8; it++) {
                float v = z[it];
                if (v > tau) { s += v; c++; }
            }
            #pragma unroll
            for (int o = 16; o; o >>= 1) {
                s += __shfl_xor_sync(0xffffffffu, s, o);
                c += __shfl_xor_sync(0xffffffffu, c, o);
            }
            if ((tid & 31) == 0) { wred[tid >> 5] = s; wcnt[tid >> 5] = c; }
            __syncthreads();
            if (tid == 0) {
                float S = 0.f; int C = 0;
                for (int w = 0; w < 16; w++) { S += wred[w]; C += wcnt[w]; }
                s_tau = (S - 1.0f) / (float)C;
            }
            __syncthreads();
            float tn = s_tau;
            if (tn == tau) break;
            tau = tn;
            __syncthreads();
        }
        if (tid == 0) g_cnt[i] = N;
        __syncthreads();
    }

    // pass C: registers -> smem (float4 layout, conflict-free) -> coalesced scalar STG
    const float tau = s_tau;
    #pragma unroll
    for (int it = 0; it < 2; it++) {
        int v = tid + it * 512;
        float4 m;
        m.x = fmaxf(z[it * 4]     - tau, 0.f);
        m.y = fmaxf(z[it * 4 + 1] - tau, 0.f);
        m.z = fmaxf(z[it * 4 + 2] - tau, 0.f);
        m.w = fmaxf(z[it * 4 + 3] - tau, 0.f);
        *(float4*)(zs + v * 4) = m;
    }
    __syncthreads();
    float* orow = outm + (size_t)i * N;
    #pragma unroll
    for (int it = 0; it < 8; it++) {
        int j = tid + it * 512;
        orow[j] = zs[j];       // 1 L1 wavefront per STG.32 (128B contiguous per warp)
    }
}

// ---------------- K2: symmetric tf32 Gram + exp + row/col partial sums (PDL secondary) ----------------
__device__ __forceinline__ void mma_tf32(float c[4], const unsigned a[4], const unsigned b[2]) {
    asm volatile(
        "mma.sync.aligned.m16n8k8.row.col.f32.tf32.tf32.f32 "
        "{%0,%1,%2,%3}, {%4,%5,%6,%7}, {%8,%9}, {%0,%1,%2,%3};\n"
        : "+f"(c[0]), "+f"(c[1]), "+f"(c[2]), "+f"(c[3])
        : "r"(a[0]), "r"(a[1]), "r"(a[2]), "r"(a[3]), "r"(b[0]), "r"(b[1]));
}

#define LDA 36

__global__ void __launch_bounds__(256) k_gemm() {
    // wait until all k_sparse blocks have published their g_ftf rows
    cudaGridDependencySynchronize();

    int t = blockIdx.x, bi = 0;
    while (t >= 32 - bi) { t -= 32 - bi; bi++; }
    const int bj = bi + t;
    const bool diag = (bi == bj);

    __shared__ __align__(16) unsigned As[128 * LDA];
    __shared__ __align__(16) unsigned Bs[128 * LDA];
    __shared__ float sZr[128];
    __shared__ float sZc[4][128];

    const int tid = threadIdx.x;
    const int lane = tid & 31, wid = tid >> 5;
    const int wm = wid >> 1, wn = wid & 1;
    const int g = lane >> 2, t4 = lane & 3;

    if (tid < 128) sZr[tid] = 0.0f;

    float acc[2][8][4];
    #pragma unroll
    for (int mt = 0; mt < 2; mt++)
        #pragma unroll
        for (int nt = 0; nt < 8; nt++)
            #pragma unroll
            for (int k = 0; k < 4; k++) acc[mt][nt][k] = 0.0f;

    const int lr = tid >> 1;
    const int lh = tid & 1;
    const unsigned* Bp = diag ? As : Bs;

    for (int kc = 0; kc < 4; kc++) {
        #pragma unroll
        for (int q = 0; q < 4; q++) {
            int cv = lh * 4 + q;
            uint4 va = *(const uint4*)(g_ftf + ((size_t)(bi * 128 + lr) * D + kc * 32 + cv * 4));
            *(uint4*)(As + lr * LDA + cv * 4) = va;
            if (!diag) {
                uint4 vb = *(const uint4*)(g_ftf + ((size_t)(bj * 128 + lr) * D + kc * 32 + cv * 4));
                *(uint4*)(Bs + lr * LDA + cv * 4) = vb;
            }
        }
        __syncthreads();

        #pragma unroll
        for (int ks = 0; ks < 4; ks++) {
            unsigned a[2][4], b[8][2];
            #pragma unroll
            for (int mt = 0; mt < 2; mt++) {
                int r0 = wm * 32 + mt * 16 + g;
                a[mt][0] = As[r0 * LDA + ks * 8 + t4];
                a[mt][1] = As[(r0 + 8) * LDA + ks * 8 + t4];
                a[mt][2] = As[r0 * LDA + ks * 8 + t4 + 4];
                a[mt][3] = As[(r0 + 8) * LDA + ks * 8 + t4 + 4];
            }
            #pragma unroll
            for (int nt = 0; nt < 8; nt++) {
                int c0 = wn * 64 + nt * 8 + g;
                b[nt][0] = Bp[c0 * LDA + ks * 8 + t4];
                b[nt][1] = Bp[c0 * LDA + ks * 8 + t4 + 4];
            }
            #pragma unroll
            for (int mt = 0; mt < 2; mt++)
                #pragma unroll
                for (int nt = 0; nt < 8; nt++) mma_tf32(acc[mt][nt], a[mt], b[nt]);
        }
        __syncthreads();
    }

    const int ibase = bi * 128, jbase = bj * 128;
    float cp0[8], cp1[8];
    #pragma unroll
    for (int nt = 0; nt < 8; nt++) { cp0[nt] = 0.f; cp1[nt] = 0.f; }

    #pragma unroll
    for (int mt = 0; mt < 2; mt++) {
        int r0 = wm * 32 + mt * 16 + g;
        int gi0 = ibase + r0, gi1 = gi0 + 8;
        float rs0 = 0.f, rs1 = 0.f;
        #pragma unroll
        for (int nt = 0; nt < 8; nt++) {
            int c0 = wn * 64 + nt * 8 + t4 * 2;
            int gj0 = jbase + c0, gj1 = gj0 + 1;
            float e0 = __expf((acc[mt][nt][0] - 1.0f) * INV_T);
            float e1 = __expf((acc[mt][nt][1] - 1.0f) * INV_T);
            float e2 = __expf((acc[mt][nt][2] - 1.0f) * INV_T);
            float e3 = __expf((acc[mt][nt][3] - 1.0f) * INV_T);
            if (diag) {
                if (gj0 == gi0) e0 = 0.f;
                if (gj1 == gi0) e1 = 0.f;
                if (gj0 == gi1) e2 = 0.f;
                if (gj1 == gi1) e3 = 0.f;
            }
            rs0 += e0 + e1; rs1 += e2 + e3;
            cp0[nt] += e0 + e2; cp1[nt] += e1 + e3;
        }
        rs0 += __shfl_xor_sync(0xffffffffu, rs0, 1);
        rs0 += __shfl_xor_sync(0xffffffffu, rs0, 2);
        rs1 += __shfl_xor_sync(0xffffffffu, rs1, 1);
        rs1 += __shfl_xor_sync(0xffffffffu, rs1, 2);
        if (t4 == 0) {
            atomicAdd(&sZr[r0], rs0);
            atomicAdd(&sZr[r0 + 8], rs1);
        }
    }

    if (!diag) {
        #pragma unroll
        for (int nt = 0; nt < 8; nt++) {
            #pragma unroll
            for (int o = 4; o <= 16; o <<= 1) {
                cp0[nt] += __shfl_xor_sync(0xffffffffu, cp0[nt], o);
                cp1[nt] += __shfl_xor_sync(0xffffffffu, cp1[nt], o);
            }
        }
        if (g == 0) {
            #pragma unroll
            for (int nt = 0; nt < 8; nt++) {
                int c = wn * 64 + nt * 8 + t4 * 2;
                sZc[wm][c] = cp0[nt];
                sZc[wm][c + 1] = cp1[nt];
            }
        }
    }
    __syncthreads();

    if (tid < 128) {
        g_partial[(size_t)(ibase + tid) * 32 + bj] = sZr[tid];
        if (!diag) {
            float cs = ((sZc[0][tid] + sZc[1][tid]) + sZc[2][tid]) + sZc[3][tid];
            g_partial[(size_t)(jbase + tid) * 32 + bi] = cs;
        }
    }
}

// ---------------- K3: per-row log-prob (warp per row) + fused final loss ----------------
__global__ void __launch_bounds__(256) k_rowfix(const float* __restrict__ outm,
                                                float* __restrict__ out, int moff) {
    const int wid = threadIdx.x >> 5, lane = threadIdx.x & 31;
    const int i = blockIdx.x * 8 + wid;

    const float4 a = *(const float4*)(g_f + (size_t)i * D + lane * 4);

    auto dot = [&](int j) -> float {
        float4 b = *(const float4*)(g_f + (size_t)j * D + lane * 4);
        float p = a.x * b.x + a.y * b.y + a.z * b.z + a.w * b.w;
        #pragma unroll
        for (int o = 16; o; o >>= 1) p += __shfl_xor_sync(0xffffffffu, p, o);
        return p;
    };

    float simpos = (dot(i ^ BHALF) - 1.0f) * INV_T;

    int cnt = g_cnt[i];
    float corr = 0.0f;
    if (cnt <= 64) {
        for (int k = 0; k < cnt; k++) {
            int j = g_sidx[i * 64 + k];
            float m = g_sval[i * 64 + k];
            corr += m * __expf((dot(j) - 1.0f) * INV_T);
        }
    } else {
        for (int j = 0; j < N; j++) {
            float m = outm[(size_t)i * N + j];
            if (m > 0.0f) corr += m * __expf((dot(j) - 1.0f) * INV_T);
        }
    }

    float zp = g_partial[(size_t)i * 32 + lane];   // one coalesced 128B line per warp
    #pragma unroll
    for (int o = 16; o; o >>= 1) zp += __shfl_xor_sync(0xffffffffu, zp, o);

    if (lane == 0) g_lp[i] = simpos - logf(zp - corr);

    // ---- last-block loss reduction (threadFenceReduction pattern; deterministic order) ----
    __syncthreads();
    __shared__ bool isLast;
    if (threadIdx.x == 0) {
        __threadfence();
        int prev = atomicAdd(&g_done, 1);
        isLast = (prev == (int)gridDim.x - 1);
    }
    __syncthreads();
    if (isLast) {
        __shared__ float sm[8];
        float s = 0.0f;
        #pragma unroll
        for (int k = 0; k < 16; k++) s += g_lp[threadIdx.x + k * 256];
        #pragma unroll
        for (int o = 16; o; o >>= 1) s += __shfl_xor_sync(0xffffffffu, s, o);
        if (lane == 0) sm[wid] = s;
        __syncthreads();
        if (threadIdx.x == 0) {
            float tot = ((sm[0] + sm[1]) + (sm[2] + sm[3])) + ((sm[4] + sm[5]) + (sm[6] + sm[7]));
            float loss = -(tot / 4096.0f);
            for (int q = 0; q < moff; q++) out[q] = loss;
            g_done = 0;   // reset for next graph replay
        }
    }
}

// ---------------- launch ----------------
extern "C" void kernel_launch(void* const* d_in, const int* in_sizes, int n_in,
                              void* d_out, int out_size) {
    int fidx = (in_sizes[0] == N * D) ? 0 : 1;
    const float* feat = (const float*)d_in[fidx];
    const float* attn = (const float*)d_in[1 - fidx];
    float* out = (float*)d_out;

    long long nn = (long long)N * (long long)N;
    int moff = (int)((long long)out_size - nn);
    if (moff < 0) moff = 0;
    float* outm = out + moff;

    k_sparse<<<N, 512>>>(feat, attn, outm);

    // k_gemm as PDL secondary: launches early, overlaps with k_sparse bulk
    cudaLaunchConfig_t cfg = {};
    cfg.gridDim = dim3(528);
    cfg.blockDim = dim3(256);
    cfg.dynamicSmemBytes = 0;
    cfg.stream = 0;
    cudaLaunchAttribute attr[1];
    attr[0].id = cudaLaunchAttributeProgrammaticStreamSerialization;
    attr[0].val.programmaticStreamSerializationAllowed = 1;
    cfg.attrs = attr;
    cfg.numAttrs = 1;
    cudaLaunchKernelEx(&cfg, k_gemm);

    k_rowfix<<<512, 256>>>(outm, out, moff);
}

// round 10
// speedup vs baseline: 1.2546x; 1.2546x over previous
#include <cuda_runtime.h>
#include <cstdint>

#define N 4096
#define D 128
#define BHALF 2048
#define INV_T 14.285714285714285714f  /* 1/0.07 */

// ---------------- scratch (static device globals; no allocation) ----------------
__device__ __align__(16) float    g_f[N * D];      // L2-normalized features, fp32
__device__ __align__(16) unsigned g_fbf[N * 64];   // packed bf16x2 (64 uints per row)
__device__ int    g_cnt[N];
__device__ int    g_sidx[N * 64];
__device__ float  g_sval[N * 64];
__device__ float  g_partial[N * 32];               // [row][slot] coalesced for rowfix
__device__ float  g_lp[N];
__device__ int    g_done;                          // zero-init; reset by last block each call

// ---------------- K1: fused L2-norm (warp 0) + row-wise sparsemax ----------------
#define CAND_MAX 128

__global__ void __launch_bounds__(512) k_sparse(const float* __restrict__ feat,
                                                const float* __restrict__ attn,
                                                float* __restrict__ outm) {
    const int i = blockIdx.x;
    const int tid = threadIdx.x;
    __shared__ __align__(16) float zs[N];          // staging for coalesced stores
    __shared__ float wred[16];
    __shared__ int   wcnt[16];
    __shared__ float s_max, s_tau;
    __shared__ int   s_ccnt, s_fb;
    __shared__ int   s_cidx[CAND_MAX];
    __shared__ float s_cval[CAND_MAX];

    // norm prologue: warp 0 normalizes feature row i (fp32 + packed bf16 copies)
    if (tid < 32) {
        float4 v = *(const float4*)(feat + (size_t)i * D + tid * 4);
        float s = v.x * v.x + v.y * v.y + v.z * v.z + v.w * v.w;
        #pragma unroll
        for (int o = 16; o; o >>= 1) s += __shfl_xor_sync(0xffffffffu, s, o);
        float r = sqrtf(s);
        float4 f = make_float4(v.x / r, v.y / r, v.z / r, v.w / r);
        *(float4*)(g_f + (size_t)i * D + tid * 4) = f;
        unsigned p0, p1;
        asm("cvt.rn.bf16x2.f32 %0, %1, %2;" : "=r"(p0) : "f"(f.y), "f"(f.x));
        asm("cvt.rn.bf16x2.f32 %0, %1, %2;" : "=r"(p1) : "f"(f.w), "f"(f.z));
        *(uint2*)(g_fbf + (size_t)i * 64 + tid * 2) = make_uint2(p0, p1);
    }

    const int j1 = i & (BHALF - 1);
    const int j2 = j1 + BHALF;
    const float4* row4 = (const float4*)(attn + (size_t)i * N);

    // pass A: streaming vectorized load, scale, mask positives/diag, track max
    float z[8];
    float mx = -3.402823466e38f;
    #pragma unroll
    for (int it = 0; it < 2; it++) {
        int v = tid + it * 512;            // float4 index 0..1023
        float4 r = __ldcs(row4 + v);
        int j = v * 4;
        float z0 = (j     == j1 || j     == j2) ? 0.f : r.x * INV_T;
        float z1 = (j + 1 == j1 || j + 1 == j2) ? 0.f : r.y * INV_T;
        float z2 = (j + 2 == j1 || j + 2 == j2) ? 0.f : r.z * INV_T;
        float z3 = (j + 3 == j1 || j + 3 == j2) ? 0.f : r.w * INV_T;
        z[it * 4] = z0; z[it * 4 + 1] = z1; z[it * 4 + 2] = z2; z[it * 4 + 3] = z3;
        mx = fmaxf(mx, fmaxf(fmaxf(z0, z1), fmaxf(z2, z3)));
    }
    #pragma unroll
    for (int o = 16; o; o >>= 1) mx = fmaxf(mx, __shfl_xor_sync(0xffffffffu, mx, o));
    if ((tid & 31) == 0) wred[tid >> 5] = mx;
    if (tid == 0) s_ccnt = 0;
    __syncthreads();
    if (tid == 0) {
        float m = wred[0];
        for (int w = 1; w < 16; w++) m = fmaxf(m, wred[w]);
        s_max = m;
    }
    __syncthreads();

    // pass B: gather candidates z >= max - 1 (sparsemax support bound)
    const float thr = s_max - 1.0f;
    #pragma unroll
    for (int it = 0; it < 2; it++) {
        int j = (tid + it * 512) * 4;
        #pragma unroll
        for (int q = 0; q < 4; q++) {
            float v = z[it * 4 + q];
            if (v >= thr) {
                int p = atomicAdd(&s_ccnt, 1);
                if (p < CAND_MAX) { s_cidx[p] = j + q; s_cval[p] = v; }
            }
        }
    }
    __syncthreads();

    if (tid == 0) {
        int cnt = s_ccnt;
        s_fb = (cnt > CAND_MAX);
        if (!s_fb) {
            // insertion sort desc by (value, index asc) -> deterministic
            for (int a = 1; a < cnt; a++) {
                float v = s_cval[a]; int ix = s_cidx[a];
                int b = a - 1;
                while (b >= 0 && (s_cval[b] < v || (s_cval[b] == v && s_cidx[b] > ix))) {
                    s_cval[b + 1] = s_cval[b]; s_cidx[b + 1] = s_cidx[b]; b--;
                }
                s_cval[b + 1] = v; s_cidx[b + 1] = ix;
            }
            // reference formula: fp32 sequential cumsum over descending values
            float cum = 0.f, cumkz = 1.f; int kz = 1;
            for (int k = 1; k <= cnt; k++) {
                float v = s_cval[k - 1];
                cum += v;
                if (1.0f + (float)k * v > cum) { kz = k; cumkz = cum; }
            }
            float tau = (cumkz - 1.0f) / (float)kz;
            s_tau = tau;
            g_cnt[i] = kz;
            int lim = kz < 64 ? kz : 64;
            for (int k = 0; k < lim; k++) {
                g_sidx[i * 64 + k] = s_cidx[k];
                g_sval[i * 64 + k] = s_cval[k] - tau;
            }
        }
    }
    __syncthreads();

    if (s_fb) {
        // fp32 Michelot fallback (safety only)
        float tau = -3.402823466e38f;
        for (int iter = 0; iter < 64; iter++) {
            float s = 0.f; int c = 0;
            #pragma unroll
            for (int it = 0; it < 8; it++) {
                float v = z[it];
                if (v > tau) { s += v; c++; }
            }
            #pragma unroll
            for (int o = 16; o; o >>= 1) {
                s += __shfl_xor_sync(0xffffffffu, s, o);
                c += __shfl_xor_sync(0xffffffffu, c, o);
            }
            if ((tid & 31) == 0) { wred[tid >> 5] = s; wcnt[tid >> 5] = c; }
            __syncthreads();
            if (tid == 0) {
                float S = 0.f; int C = 0;
                for (int w = 0; w < 16; w++) { S += wred[w]; C += wcnt[w]; }
                s_tau = (S - 1.0f) / (float)C;
            }
            __syncthreads();
            float tn = s_tau;
            if (tn == tau) break;
            tau = tn;
            __syncthreads();
        }
        if (tid == 0) g_cnt[i] = N;
        __syncthreads();
    }

    // pass C: registers -> smem (float4 layout) -> coalesced streaming scalar STG
    const float tau = s_tau;
    #pragma unroll
    for (int it = 0; it < 2; it++) {
        int v = tid + it * 512;
        float4 m;
        m.x = fmaxf(z[it * 4]     - tau, 0.f);
        m.y = fmaxf(z[it * 4 + 1] - tau, 0.f);
        m.z = fmaxf(z[it * 4 + 2] - tau, 0.f);
        m.w = fmaxf(z[it * 4 + 3] - tau, 0.f);
        *(float4*)(zs + v * 4) = m;
    }
    __syncthreads();
    float* orow = outm + (size_t)i * N;
    #pragma unroll
    for (int it = 0; it < 8; it++) {
        int j = tid + it * 512;
        __stcs(orow + j, zs[j]);   // coalesced 128B/warp, evict-first
    }
}

// ---------------- K2: symmetric bf16 Gram + exp + row/col partial sums ----------------
__device__ __forceinline__ void mma_bf16(float c[4], const unsigned a[4], const unsigned b[2]) {
    asm volatile(
        "mma.sync.aligned.m16n8k16.row.col.f32.bf16.bf16.f32 "
        "{%0,%1,%2,%3}, {%4,%5,%6,%7}, {%8,%9}, {%0,%1,%2,%3};\n"
        : "+f"(c[0]), "+f"(c[1]), "+f"(c[2]), "+f"(c[3])
        : "r"(a[0]), "r"(a[1]), "r"(a[2]), "r"(a[3]), "r"(b[0]), "r"(b[1]));
}

#define LDA 36

__global__ void __launch_bounds__(256) k_gemm() {
    int t = blockIdx.x, bi = 0;
    while (t >= 32 - bi) { t -= 32 - bi; bi++; }
    const int bj = bi + t;
    const bool diag = (bi == bj);

    __shared__ __align__(16) unsigned As[128 * LDA];
    __shared__ __align__(16) unsigned Bs[128 * LDA];
    __shared__ float sZr[128];
    __shared__ float sZc[4][128];

    const int tid = threadIdx.x;
    const int lane = tid & 31, wid = tid >> 5;
    const int wm = wid >> 1, wn = wid & 1;
    const int g = lane >> 2, t4 = lane & 3;

    if (tid < 128) sZr[tid] = 0.0f;

    float acc[2][8][4];
    #pragma unroll
    for (int mt = 0; mt < 2; mt++)
        #pragma unroll
        for (int nt = 0; nt < 8; nt++)
            #pragma unroll
            for (int k = 0; k < 4; k++) acc[mt][nt][k] = 0.0f;

    const int lr = tid >> 1;
    const int lh = tid & 1;
    const unsigned* Bp = diag ? As : Bs;

    // 2 k-chunks of 64 bf16 (= 32 packed uints) each
    for (int kc = 0; kc < 2; kc++) {
        #pragma unroll
        for (int q = 0; q < 4; q++) {
            int cv = lh * 4 + q;           // uint4 index 0..7 within 32-uint chunk
            uint4 va = *(const uint4*)(g_fbf + ((size_t)(bi * 128 + lr) * 64 + kc * 32 + cv * 4));
            *(uint4*)(As + lr * LDA + cv * 4) = va;
            if (!diag) {
                uint4 vb = *(const uint4*)(g_fbf + ((size_t)(bj * 128 + lr) * 64 + kc * 32 + cv * 4));
                *(uint4*)(Bs + lr * LDA + cv * 4) = vb;
            }
        }
        __syncthreads();

        #pragma unroll
        for (int ks = 0; ks < 4; ks++) {   // k16 steps within the k64 chunk
            unsigned a[2][4], b[8][2];
            #pragma unroll
            for (int mt = 0; mt < 2; mt++) {
                int r0 = wm * 32 + mt * 16 + g;
                a[mt][0] = As[r0 * LDA + ks * 8 + t4];
                a[mt][1] = As[(r0 + 8) * LDA + ks * 8 + t4];
                a[mt][2] = As[r0 * LDA + ks * 8 + t4 + 4];
                a[mt][3] = As[(r0 + 8) * LDA + ks * 8 + t4 + 4];
            }
            #pragma unroll
            for (int nt = 0; nt < 8; nt++) {
                int c0 = wn * 64 + nt * 8 + g;
                b[nt][0] = Bp[c0 * LDA + ks * 8 + t4];
                b[nt][1] = Bp[c0 * LDA + ks * 8 + t4 + 4];
            }
            #pragma unroll
            for (int mt = 0; mt < 2; mt++)
                #pragma unroll
                for (int nt = 0; nt < 8; nt++) mma_bf16(acc[mt][nt], a[mt], b[nt]);
        }
        __syncthreads();
    }

    const int ibase = bi * 128, jbase = bj * 128;
    float cp0[8], cp1[8];
    #pragma unroll
    for (int nt = 0; nt < 8; nt++) { cp0[nt] = 0.f; cp1[nt] = 0.f; }

    #pragma unroll
    for (int mt = 0; mt < 2; mt++) {
        int r0 = wm * 32 + mt * 16 + g;
        int gi0 = ibase + r0, gi1 = gi0 + 8;
        float rs0 = 0.f, rs1 = 0.f;
        #pragma unroll
        for (int nt = 0; nt < 8; nt++) {
            int c0 = wn * 64 + nt * 8 + t4 * 2;
            int gj0 = jbase + c0, gj1 = gj0 + 1;
            float e0 = __expf((acc[mt][nt][0] - 1.0f) * INV_T);
            float e1 = __expf((acc[mt][nt][1] - 1.0f) * INV_T);
            float e2 = __expf((acc[mt][nt][2] - 1.0f) * INV_T);
            float e3 = __expf((acc[mt][nt][3] - 1.0f) * INV_T);
            if (diag) {
                if (gj0 == gi0) e0 = 0.f;
                if (gj1 == gi0) e1 = 0.f;
                if (gj0 == gi1) e2 = 0.f;
                if (gj1 == gi1) e3 = 0.f;
            }
            rs0 += e0 + e1; rs1 += e2 + e3;
            cp0[nt] += e0 + e2; cp1[nt] += e1 + e3;
        }
        rs0 += __shfl_xor_sync(0xffffffffu, rs0, 1);
        rs0 += __shfl_xor_sync(0xffffffffu, rs0, 2);
        rs1 += __shfl_xor_sync(0xffffffffu, rs1, 1);
        rs1 += __shfl_xor_sync(0xffffffffu, rs1, 2);
        if (t4 == 0) {
            atomicAdd(&sZr[r0], rs0);
            atomicAdd(&sZr[r0 + 8], rs1);
        }
    }

    if (!diag) {
        #pragma unroll
        for (int nt = 0; nt < 8; nt++) {
            #pragma unroll
            for (int o = 4; o <= 16; o <<= 1) {
                cp0[nt] += __shfl_xor_sync(0xffffffffu, cp0[nt], o);
                cp1[nt] += __shfl_xor_sync(0xffffffffu, cp1[nt], o);
            }
        }
        if (g == 0) {
            #pragma unroll
            for (int nt = 0; nt < 8; nt++) {
                int c = wn * 64 + nt * 8 + t4 * 2;
                sZc[wm][c] = cp0[nt];
                sZc[wm][c + 1] = cp1[nt];
            }
        }
    }
    __syncthreads();

    if (tid < 128) {
        g_partial[(size_t)(ibase + tid) * 32 + bj] = sZr[tid];
        if (!diag) {
            float cs = ((sZc[0][tid] + sZc[1][tid]) + sZc[2][tid]) + sZc[3][tid];
            g_partial[(size_t)(jbase + tid) * 32 + bi] = cs;
        }
    }
}

// ---------------- K3: per-row log-prob (warp per row) + fused final loss ----------------
__global__ void __launch_bounds__(256) k_rowfix(const float* __restrict__ outm,
                                                float* __restrict__ out, int moff) {
    const int wid = threadIdx.x >> 5, lane = threadIdx.x & 31;
    const int i = blockIdx.x * 8 + wid;

    const float4 a = *(const float4*)(g_f + (size_t)i * D + lane * 4);

    auto dot = [&](int j) -> float {
        float4 b = *(const float4*)(g_f + (size_t)j * D + lane * 4);
        float p = a.x * b.x + a.y * b.y + a.z * b.z + a.w * b.w;
        #pragma unroll
        for (int o = 16; o; o >>= 1) p += __shfl_xor_sync(0xffffffffu, p, o);
        return p;
    };

    // corr must match gemm's bf16-level sim so Z - corr is consistent:
    // recompute those dots from the bf16-rounded values (g_fbf) in fp32.
    auto dotbf = [&](int j) -> float {
        uint2 pa = *(const uint2*)(g_fbf + (size_t)i * 64 + lane * 2);
        uint2 pb = *(const uint2*)(g_fbf + (size_t)j * 64 + lane * 2);
        float ax0 = __uint_as_float(pa.x << 16), ax1 = __uint_as_float(pa.x & 0xffff0000u);
        float ay0 = __uint_as_float(pa.y << 16), ay1 = __uint_as_float(pa.y & 0xffff0000u);
        float bx0 = __uint_as_float(pb.x << 16), bx1 = __uint_as_float(pb.x & 0xffff0000u);
        float by0 = __uint_as_float(pb.y << 16), by1 = __uint_as_float(pb.y & 0xffff0000u);
        float p = ax0 * bx0 + ax1 * bx1 + ay0 * by0 + ay1 * by1;
        #pragma unroll
        for (int o = 16; o; o >>= 1) p += __shfl_xor_sync(0xffffffffu, p, o);
        return p;
    };

    float simpos = (dot(i ^ BHALF) - 1.0f) * INV_T;

    int cnt = g_cnt[i];
    float corr = 0.0f;
    if (cnt <= 64) {
        for (int k = 0; k < cnt; k++) {
            int j = g_sidx[i * 64 + k];
            float m = g_sval[i * 64 + k];
            corr += m * __expf((dotbf(j) - 1.0f) * INV_T);
        }
    } else {
        for (int j = 0; j < N; j++) {
            float m = outm[(size_t)i * N + j];
            if (m > 0.0f) corr += m * __expf((dotbf(j) - 1.0f) * INV_T);
        }
    }

    float zp = g_partial[(size_t)i * 32 + lane];   // one coalesced 128B line per warp
    #pragma unroll
    for (int o = 16; o; o >>= 1) zp += __shfl_xor_sync(0xffffffffu, zp, o);

    if (lane == 0) g_lp[i] = simpos - logf(zp - corr);

    // ---- last-block loss reduction (threadFenceReduction pattern; deterministic order) ----
    __syncthreads();
    __shared__ bool isLast;
    if (threadIdx.x == 0) {
        __threadfence();
        int prev = atomicAdd(&g_done, 1);
        isLast = (prev == (int)gridDim.x - 1);
    }
    __syncthreads();
    if (isLast) {
        __shared__ float sm[8];
        float s = 0.0f;
        #pragma unroll
        for (int k = 0; k < 16; k++) s += g_lp[threadIdx.x + k * 256];
        #pragma unroll
        for (int o = 16; o; o >>= 1) s += __shfl_xor_sync(0xffffffffu, s, o);
        if (lane == 0) sm[wid] = s;
        __syncthreads();
        if (threadIdx.x == 0) {
            float tot = ((sm[0] + sm[1]) + (sm[2] + sm[3])) + ((sm[4] + sm[5]) + (sm[6] + sm[7]));
            float loss = -(tot / 4096.0f);
            for (int q = 0; q < moff; q++) out[q] = loss;
            g_done = 0;   // reset for next graph replay
        }
    }
}

// ---------------- launch ----------------
extern "C" void kernel_launch(void* const* d_in, const int* in_sizes, int n_in,
                              void* d_out, int out_size) {
    int fidx = (in_sizes[0] == N * D) ? 0 : 1;
    const float* feat = (const float*)d_in[fidx];
    const float* attn = (const float*)d_in[1 - fidx];
    float* out = (float*)d_out;

    long long nn = (long long)N * (long long)N;
    int moff = (int)((long long)out_size - nn);
    if (moff < 0) moff = 0;
    float* outm = out + moff;

    k_sparse<<<N, 512>>>(feat, attn, outm);
    k_gemm<<<528, 256>>>();
    k_rowfix<<<512, 256>>>(outm, out, moff);
}

// round 11
// speedup vs baseline: 1.2973x; 1.0340x over previous
#include <cuda_runtime.h>
#include <cstdint>

#define N 4096
#define D 128
#define BHALF 2048
#define INV_T 14.285714285714285714f  /* 1/0.07 */

// ---------------- scratch (static device globals; no allocation) ----------------
__device__ __align__(16) float    g_f[N * D];      // L2-normalized features, fp32
__device__ __align__(16) unsigned g_fbf[N * 64];   // packed bf16x2 (64 uints per row)
__device__ int    g_cnt[N];
__device__ int    g_sidx[N * 64];
__device__ float  g_sval[N * 64];
__device__ float  g_partial[N * 32];               // [row][slot] coalesced for rowfix
__device__ float  g_lp[N];
__device__ int    g_done;                          // zero-init; reset by last block each call

// ---------------- K1: fused L2-norm (warp 0) + row-wise sparsemax ----------------
#define CAND_MAX 128

__global__ void __launch_bounds__(512, 4) k_sparse(const float* __restrict__ feat,
                                                   const float* __restrict__ attn,
                                                   float* __restrict__ outm) {
    const int i = blockIdx.x;
    const int tid = threadIdx.x;
    __shared__ __align__(16) float zs[N];          // staging for coalesced stores
    __shared__ float wred[16];
    __shared__ int   wcnt[16];
    __shared__ float s_tau;
    __shared__ int   s_ccnt, s_fb;
    __shared__ int   s_cidx[CAND_MAX];
    __shared__ float s_cval[CAND_MAX];

    // norm prologue: warp 0 normalizes feature row i (fp32 + packed bf16 copies)
    if (tid < 32) {
        float4 v = *(const float4*)(feat + (size_t)i * D + tid * 4);
        float s = v.x * v.x + v.y * v.y + v.z * v.z + v.w * v.w;
        #pragma unroll
        for (int o = 16; o; o >>= 1) s += __shfl_xor_sync(0xffffffffu, s, o);
        float r = sqrtf(s);
        float4 f = make_float4(v.x / r, v.y / r, v.z / r, v.w / r);
        *(float4*)(g_f + (size_t)i * D + tid * 4) = f;
        unsigned p0, p1;
        asm("cvt.rn.bf16x2.f32 %0, %1, %2;" : "=r"(p0) : "f"(f.y), "f"(f.x));
        asm("cvt.rn.bf16x2.f32 %0, %1, %2;" : "=r"(p1) : "f"(f.w), "f"(f.z));
        *(uint2*)(g_fbf + (size_t)i * 64 + tid * 2) = make_uint2(p0, p1);
    }

    const int j1 = i & (BHALF - 1);        // in [0, 2048)
    const int j2 = j1 + BHALF;             // in [2048, 4096)
    const float4* row4 = (const float4*)(attn + (size_t)i * N);

    // pass A: streaming vectorized load, scale, mask (half-specific compare), warp max
    float z[8];
    float mx = -3.402823466e38f;
    {
        // it = 0: element indices < 2048, can only hit j1
        int v = tid;
        float4 r = __ldcs(row4 + v);
        int j = v * 4;
        float z0 = (j     == j1) ? 0.f : r.x * INV_T;
        float z1 = (j + 1 == j1) ? 0.f : r.y * INV_T;
        float z2 = (j + 2 == j1) ? 0.f : r.z * INV_T;
        float z3 = (j + 3 == j1) ? 0.f : r.w * INV_T;
        z[0] = z0; z[1] = z1; z[2] = z2; z[3] = z3;
        mx = fmaxf(mx, fmaxf(fmaxf(z0, z1), fmaxf(z2, z3)));
        // it = 1: element indices >= 2048, can only hit j2
        v = tid + 512;
        r = __ldcs(row4 + v);
        j = v * 4;
        z0 = (j     == j2) ? 0.f : r.x * INV_T;
        z1 = (j + 1 == j2) ? 0.f : r.y * INV_T;
        z2 = (j + 2 == j2) ? 0.f : r.z * INV_T;
        z3 = (j + 3 == j2) ? 0.f : r.w * INV_T;
        z[4] = z0; z[5] = z1; z[6] = z2; z[7] = z3;
        mx = fmaxf(mx, fmaxf(fmaxf(z0, z1), fmaxf(z2, z3)));
    }
    #pragma unroll
    for (int o = 16; o; o >>= 1) mx = fmaxf(mx, __shfl_xor_sync(0xffffffffu, mx, o));
    if ((tid & 31) == 0) wred[tid >> 5] = mx;
    if (tid == 0) s_ccnt = 0;
    __syncthreads();                               // B1

    // every thread reduces the 16 warp maxima itself (broadcast LDS, no extra barrier)
    float bm = wred[0];
    #pragma unroll
    for (int w = 1; w < 16; w++) bm = fmaxf(bm, wred[w]);
    const float thr = bm - 1.0f;                   // sparsemax support bound: tau >= max-1

    // pass B: gather candidates z >= thr
    #pragma unroll
    for (int it = 0; it < 2; it++) {
        int j = (tid + it * 512) * 4;
        #pragma unroll
        for (int q = 0; q < 4; q++) {
            float v = z[it * 4 + q];
            if (v >= thr) {
                int p = atomicAdd(&s_ccnt, 1);
                if (p < CAND_MAX) { s_cidx[p] = j + q; s_cval[p] = v; }
            }
        }
    }
    __syncthreads();                               // B2

    if (tid == 0) {
        int cnt = s_ccnt;
        s_fb = (cnt > CAND_MAX);
        if (!s_fb) {
            // insertion sort desc by (value, index asc) -> deterministic
            for (int a = 1; a < cnt; a++) {
                float v = s_cval[a]; int ix = s_cidx[a];
                int b = a - 1;
                while (b >= 0 && (s_cval[b] < v || (s_cval[b] == v && s_cidx[b] > ix))) {
                    s_cval[b + 1] = s_cval[b]; s_cidx[b + 1] = s_cidx[b]; b--;
                }
                s_cval[b + 1] = v; s_cidx[b + 1] = ix;
            }
            // reference formula: fp32 sequential cumsum over descending values
            float cum = 0.f, cumkz = 1.f; int kz = 1;
            for (int k = 1; k <= cnt; k++) {
                float v = s_cval[k - 1];
                cum += v;
                if (1.0f + (float)k * v > cum) { kz = k; cumkz = cum; }
            }
            float tau = (cumkz - 1.0f) / (float)kz;
            s_tau = tau;
            g_cnt[i] = kz;
            int lim = kz < 64 ? kz : 64;
            for (int k = 0; k < lim; k++) {
                g_sidx[i * 64 + k] = s_cidx[k];
                g_sval[i * 64 + k] = s_cval[k] - tau;
            }
        }
    }
    __syncthreads();                               // B3

    if (s_fb) {
        // fp32 Michelot fallback (safety only)
        float tau = -3.402823466e38f;
        for (int iter = 0; iter < 64; iter++) {
            float s = 0.f; int c = 0;
            #pragma unroll
            for (int it = 0; it < 8; it++) {
                float v = z[it];
                if (v > tau) { s += v; c++; }
            }
            #pragma unroll
            for (int o = 16; o; o >>= 1) {
                s += __shfl_xor_sync(0xffffffffu, s, o);
                c += __shfl_xor_sync(0xffffffffu, c, o);
            }
            if ((tid & 31) == 0) { wred[tid >> 5] = s; wcnt[tid >> 5] = c; }
            __syncthreads();
            if (tid == 0) {
                float S = 0.f; int C = 0;
                for (int w = 0; w < 16; w++) { S += wred[w]; C += wcnt[w]; }
                s_tau = (S - 1.0f) / (float)C;
            }
            __syncthreads();
            float tn = s_tau;
            if (tn == tau) break;
            tau = tn;
            __syncthreads();
        }
        if (tid == 0) g_cnt[i] = N;
        __syncthreads();
    }

    // pass C: registers -> smem (float4 layout) -> coalesced streaming scalar STG
    const float tau = s_tau;
    #pragma unroll
    for (int it = 0; it < 2; it++) {
        int v = tid + it * 512;
        float4 m;
        m.x = fmaxf(z[it * 4]     - tau, 0.f);
        m.y = fmaxf(z[it * 4 + 1] - tau, 0.f);
        m.z = fmaxf(z[it * 4 + 2] - tau, 0.f);
        m.w = fmaxf(z[it * 4 + 3] - tau, 0.f);
        *(float4*)(zs + v * 4) = m;
    }
    __syncthreads();                               // B4
    float* orow = outm + (size_t)i * N;
    #pragma unroll
    for (int it = 0; it < 8; it++) {
        int j = tid + it * 512;
        __stcs(orow + j, zs[j]);   // coalesced 128B/warp, evict-first
    }
}

// ---------------- K2: symmetric bf16 Gram + exp + row/col partial sums ----------------
__device__ __forceinline__ void mma_bf16(float c[4], const unsigned a[4], const unsigned b[2]) {
    asm volatile(
        "mma.sync.aligned.m16n8k16.row.col.f32.bf16.bf16.f32 "
        "{%0,%1,%2,%3}, {%4,%5,%6,%7}, {%8,%9}, {%0,%1,%2,%3};\n"
        : "+f"(c[0]), "+f"(c[1]), "+f"(c[2]), "+f"(c[3])
        : "r"(a[0]), "r"(a[1]), "r"(a[2]), "r"(a[3]), "r"(b[0]), "r"(b[1]));
}

#define LDA 36

__global__ void __launch_bounds__(256) k_gemm() {
    int t = blockIdx.x, bi = 0;
    while (t >= 32 - bi) { t -= 32 - bi; bi++; }
    const int bj = bi + t;
    const bool diag = (bi == bj);

    __shared__ __align__(16) unsigned As[128 * LDA];
    __shared__ __align__(16) unsigned Bs[128 * LDA];
    __shared__ float sZr[128];
    __shared__ float sZc[4][128];

    const int tid = threadIdx.x;
    const int lane = tid & 31, wid = tid >> 5;
    const int wm = wid >> 1, wn = wid & 1;
    const int g = lane >> 2, t4 = lane & 3;

    if (tid < 128) sZr[tid] = 0.0f;

    float acc[2][8][4];
    #pragma unroll
    for (int mt = 0; mt < 2; mt++)
        #pragma unroll
        for (int nt = 0; nt < 8; nt++)
            #pragma unroll
            for (int k = 0; k < 4; k++) acc[mt][nt][k] = 0.0f;

    const int lr = tid >> 1;
    const int lh = tid & 1;
    const unsigned* Bp = diag ? As : Bs;

    // 2 k-chunks of 64 bf16 (= 32 packed uints) each
    for (int kc = 0; kc < 2; kc++) {
        #pragma unroll
        for (int q = 0; q < 4; q++) {
            int cv = lh * 4 + q;
            uint4 va = *(const uint4*)(g_fbf + ((size_t)(bi * 128 + lr) * 64 + kc * 32 + cv * 4));
            *(uint4*)(As + lr * LDA + cv * 4) = va;
            if (!diag) {
                uint4 vb = *(const uint4*)(g_fbf + ((size_t)(bj * 128 + lr) * 64 + kc * 32 + cv * 4));
                *(uint4*)(Bs + lr * LDA + cv * 4) = vb;
            }
        }
        __syncthreads();

        #pragma unroll
        for (int ks = 0; ks < 4; ks++) {
            unsigned a[2][4], b[8][2];
            #pragma unroll
            for (int mt = 0; mt < 2; mt++) {
                int r0 = wm * 32 + mt * 16 + g;
                a[mt][0] = As[r0 * LDA + ks * 8 + t4];
                a[mt][1] = As[(r0 + 8) * LDA + ks * 8 + t4];
                a[mt][2] = As[r0 * LDA + ks * 8 + t4 + 4];
                a[mt][3] = As[(r0 + 8) * LDA + ks * 8 + t4 + 4];
            }
            #pragma unroll
            for (int nt = 0; nt < 8; nt++) {
                int c0 = wn * 64 + nt * 8 + g;
                b[nt][0] = Bp[c0 * LDA + ks * 8 + t4];
                b[nt][1] = Bp[c0 * LDA + ks * 8 + t4 + 4];
            }
            #pragma unroll
            for (int mt = 0; mt < 2; mt++)
                #pragma unroll
                for (int nt = 0; nt < 8; nt++) mma_bf16(acc[mt][nt], a[mt], b[nt]);
        }
        __syncthreads();
    }

    const int ibase = bi * 128, jbase = bj * 128;
    float cp0[8], cp1[8];
    #pragma unroll
    for (int nt = 0; nt < 8; nt++) { cp0[nt] = 0.f; cp1[nt] = 0.f; }

    #pragma unroll
    for (int mt = 0; mt < 2; mt++) {
        int r0 = wm * 32 + mt * 16 + g;
        int gi0 = ibase + r0, gi1 = gi0 + 8;
        float rs0 = 0.f, rs1 = 0.f;
        #pragma unroll
        for (int nt = 0; nt < 8; nt++) {
            int c0 = wn * 64 + nt * 8 + t4 * 2;
            int gj0 = jbase + c0, gj1 = gj0 + 1;
            float e0 = __expf((acc[mt][nt][0] - 1.0f) * INV_T);
            float e1 = __expf((acc[mt][nt][1] - 1.0f) * INV_T);
            float e2 = __expf((acc[mt][nt][2] - 1.0f) * INV_T);
            float e3 = __expf((acc[mt][nt][3] - 1.0f) * INV_T);
            if (diag) {
                if (gj0 == gi0) e0 = 0.f;
                if (gj1 == gi0) e1 = 0.f;
                if (gj0 == gi1) e2 = 0.f;
                if (gj1 == gi1) e3 = 0.f;
            }
            rs0 += e0 + e1; rs1 += e2 + e3;
            cp0[nt] += e0 + e2; cp1[nt] += e1 + e3;
        }
        rs0 += __shfl_xor_sync(0xffffffffu, rs0, 1);
        rs0 += __shfl_xor_sync(0xffffffffu, rs0, 2);
        rs1 += __shfl_xor_sync(0xffffffffu, rs1, 1);
        rs1 += __shfl_xor_sync(0xffffffffu, rs1, 2);
        if (t4 == 0) {
            atomicAdd(&sZr[r0], rs0);
            atomicAdd(&sZr[r0 + 8], rs1);
        }
    }

    if (!diag) {
        #pragma unroll
        for (int nt = 0; nt < 8; nt++) {
            #pragma unroll
            for (int o = 4; o <= 16; o <<= 1) {
                cp0[nt] += __shfl_xor_sync(0xffffffffu, cp0[nt], o);
                cp1[nt] += __shfl_xor_sync(0xffffffffu, cp1[nt], o);
            }
        }
        if (g == 0) {
            #pragma unroll
            for (int nt = 0; nt < 8; nt++) {
                int c = wn * 64 + nt * 8 + t4 * 2;
                sZc[wm][c] = cp0[nt];
                sZc[wm][c + 1] = cp1[nt];
            }
        }
    }
    __syncthreads();

    if (tid < 128) {
        g_partial[(size_t)(ibase + tid) * 32 + bj] = sZr[tid];
        if (!diag) {
            float cs = ((sZc[0][tid] + sZc[1][tid]) + sZc[2][tid]) + sZc[3][tid];
            g_partial[(size_t)(jbase + tid) * 32 + bi] = cs;
        }
    }
}

// ---------------- K3: per-row log-prob (warp per row) + fused final loss ----------------
__global__ void __launch_bounds__(256) k_rowfix(const float* __restrict__ outm,
                                                float* __restrict__ out, int moff) {
    const int wid = threadIdx.x >> 5, lane = threadIdx.x & 31;
    const int i = blockIdx.x * 8 + wid;

    const float4 a = *(const float4*)(g_f + (size_t)i * D + lane * 4);

    auto dot = [&](int j) -> float {
        float4 b = *(const float4*)(g_f + (size_t)j * D + lane * 4);
        float p = a.x * b.x + a.y * b.y + a.z * b.z + a.w * b.w;
        #pragma unroll
        for (int o = 16; o; o >>= 1) p += __shfl_xor_sync(0xffffffffu, p, o);
        return p;
    };

    // corr must match gemm's bf16-level sim so Z - corr is consistent
    auto dotbf = [&](int j) -> float {
        uint2 pa = *(const uint2*)(g_fbf + (size_t)i * 64 + lane * 2);
        uint2 pb = *(const uint2*)(g_fbf + (size_t)j * 64 + lane * 2);
        float ax0 = __uint_as_float(pa.x << 16), ax1 = __uint_as_float(pa.x & 0xffff0000u);
        float ay0 = __uint_as_float(pa.y << 16), ay1 = __uint_as_float(pa.y & 0xffff0000u);
        float bx0 = __uint_as_float(pb.x << 16), bx1 = __uint_as_float(pb.x & 0xffff0000u);
        float by0 = __uint_as_float(pb.y << 16), by1 = __uint_as_float(pb.y & 0xffff0000u);
        float p = ax0 * bx0 + ax1 * bx1 + ay0 * by0 + ay1 * by1;
        #pragma unroll
        for (int o = 16; o; o >>= 1) p += __shfl_xor_sync(0xffffffffu, p, o);
        return p;
    };

    float simpos = (dot(i ^ BHALF) - 1.0f) * INV_T;

    int cnt = g_cnt[i];
    float corr = 0.0f;
    if (cnt <= 64) {
        for (int k = 0; k < cnt; k++) {
            int j = g_sidx[i * 64 + k];
            float m = g_sval[i * 64 + k];
            corr += m * __expf((dotbf(j) - 1.0f) * INV_T);
        }
    } else {
        for (int j = 0; j < N; j++) {
            float m = outm[(size_t)i * N + j];
            if (m > 0.0f) corr += m * __expf((dotbf(j) - 1.0f) * INV_T);
        }
    }

    float zp = g_partial[(size_t)i * 32 + lane];   // one coalesced 128B line per warp
    #pragma unroll
    for (int o = 16; o; o >>= 1) zp += __shfl_xor_sync(0xffffffffu, zp, o);

    if (lane == 0) g_lp[i] = simpos - logf(zp - corr);

    // ---- last-block loss reduction (threadFenceReduction pattern; deterministic order) ----
    __syncthreads();
    __shared__ bool isLast;
    if (threadIdx.x == 0) {
        __threadfence();
        int prev = atomicAdd(&g_done, 1);
        isLast = (prev == (int)gridDim.x - 1);
    }
    __syncthreads();
    if (isLast) {
        __shared__ float sm[8];
        float s = 0.0f;
        #pragma unroll
        for (int k = 0; k < 16; k++) s += g_lp[threadIdx.x + k * 256];
        #pragma unroll
        for (int o = 16; o; o >>= 1) s += __shfl_xor_sync(0xffffffffu, s, o);
        if (lane == 0) sm[wid] = s;
        __syncthreads();
        if (threadIdx.x == 0) {
            float tot = ((sm[0] + sm[1]) + (sm[2] + sm[3])) + ((sm[4] + sm[5]) + (sm[6] + sm[7]));
            float loss = -(tot / 4096.0f);
            for (int q = 0; q < moff; q++) out[q] = loss;
            g_done = 0;   // reset for next graph replay
        }
    }
}

// ---------------- launch ----------------
extern "C" void kernel_launch(void* const* d_in, const int* in_sizes, int n_in,
                              void* d_out, int out_size) {
    int fidx = (in_sizes[0] == N * D) ? 0 : 1;
    const float* feat = (const float*)d_in[fidx];
    const float* attn = (const float*)d_in[1 - fidx];
    float* out = (float*)d_out;

    long long nn = (long long)N * (long long)N;
    int moff = (int)((long long)out_size - nn);
    if (moff < 0) moff = 0;
    float* outm = out + moff;

    k_sparse<<<N, 512>>>(feat, attn, outm);
    k_gemm<<<528, 256>>>();
    k_rowfix<<<512, 256>>>(outm, out, moff);
}

// round 12
// speedup vs baseline: 1.3498x; 1.0404x over previous
#include <cuda_runtime.h>
#include <cstdint>

#define N 4096
#define D 128
#define BHALF 2048
#define INV_T 14.285714285714285714f  /* 1/0.07 */

// ---------------- scratch (static device globals; no allocation) ----------------
__device__ __align__(16) float    g_f[N * D];      // L2-normalized features, fp32
__device__ __align__(16) unsigned g_fbf[N * 64];   // packed bf16x2 (64 uints per row)
__device__ int    g_cnt[N];
__device__ int    g_sidx[N * 64];
__device__ float  g_sval[N * 64];
__device__ float  g_partial[N * 32];               // [row][slot] coalesced for rowfix
__device__ float  g_lp[N];
__device__ int    g_done;                          // zero-init; reset by last block each call

// ---------------- K1: fused L2-norm (warp 0) + row-wise sparsemax ----------------
#define CAND_MAX 128

__global__ void __launch_bounds__(512, 4) k_sparse(const float* __restrict__ feat,
                                                   const float* __restrict__ attn,
                                                   float* __restrict__ outm) {
    const int i = blockIdx.x;
    const int tid = threadIdx.x;
    __shared__ float wred[16];
    __shared__ int   wcnt[16];
    __shared__ float s_tau;
    __shared__ int   s_ccnt, s_fb;
    __shared__ int   s_cidx[CAND_MAX];
    __shared__ float s_cval[CAND_MAX];

    // norm prologue: warp 0 normalizes feature row i (fp32 + packed bf16 copies)
    if (tid < 32) {
        float4 v = *(const float4*)(feat + (size_t)i * D + tid * 4);
        float s = v.x * v.x + v.y * v.y + v.z * v.z + v.w * v.w;
        #pragma unroll
        for (int o = 16; o; o >>= 1) s += __shfl_xor_sync(0xffffffffu, s, o);
        float r = sqrtf(s);
        float4 f = make_float4(v.x / r, v.y / r, v.z / r, v.w / r);
        *(float4*)(g_f + (size_t)i * D + tid * 4) = f;
        unsigned p0, p1;
        asm("cvt.rn.bf16x2.f32 %0, %1, %2;" : "=r"(p0) : "f"(f.y), "f"(f.x));
        asm("cvt.rn.bf16x2.f32 %0, %1, %2;" : "=r"(p1) : "f"(f.w), "f"(f.z));
        *(uint2*)(g_fbf + (size_t)i * 64 + tid * 2) = make_uint2(p0, p1);
    }

    const int j1 = i & (BHALF - 1);        // in [0, 2048)
    const int j2 = j1 + BHALF;             // in [2048, 4096)
    const float* row = attn + (size_t)i * N;

    // pass A: coalesced scalar streaming loads (register resident), mask, warp max
    // it < 4 covers j in [0,2048) -> only j1 possible; it >= 4 -> only j2
    float z[8];
    float mx = -3.402823466e38f;
    #pragma unroll
    for (int it = 0; it < 8; it++) {
        int j = tid + it * 512;
        float v = __ldcs(row + j) * INV_T;
        if (it < 4) { if (j == j1) v = 0.f; }
        else        { if (j == j2) v = 0.f; }
        z[it] = v;
        mx = fmaxf(mx, v);
    }
    #pragma unroll
    for (int o = 16; o; o >>= 1) mx = fmaxf(mx, __shfl_xor_sync(0xffffffffu, mx, o));
    if ((tid & 31) == 0) wred[tid >> 5] = mx;
    if (tid == 0) s_ccnt = 0;
    __syncthreads();                               // B1

    // every thread reduces the 16 warp maxima itself (broadcast LDS)
    float bm = wred[0];
    #pragma unroll
    for (int w = 1; w < 16; w++) bm = fmaxf(bm, wred[w]);
    const float thr = bm - 1.0f;                   // sparsemax support bound: tau >= max-1

    // pass B: gather candidates z >= thr
    #pragma unroll
    for (int it = 0; it < 8; it++) {
        float v = z[it];
        if (v >= thr) {
            int p = atomicAdd(&s_ccnt, 1);
            if (p < CAND_MAX) { s_cidx[p] = tid + it * 512; s_cval[p] = v; }
        }
    }
    __syncthreads();                               // B2

    if (tid == 0) {
        int cnt = s_ccnt;
        s_fb = (cnt > CAND_MAX);
        if (!s_fb) {
            // insertion sort desc by (value, index asc) -> deterministic
            for (int a = 1; a < cnt; a++) {
                float v = s_cval[a]; int ix = s_cidx[a];
                int b = a - 1;
                while (b >= 0 && (s_cval[b] < v || (s_cval[b] == v && s_cidx[b] > ix))) {
                    s_cval[b + 1] = s_cval[b]; s_cidx[b + 1] = s_cidx[b]; b--;
                }
                s_cval[b + 1] = v; s_cidx[b + 1] = ix;
            }
            // reference formula: fp32 sequential cumsum over descending values
            float cum = 0.f, cumkz = 1.f; int kz = 1;
            for (int k = 1; k <= cnt; k++) {
                float v = s_cval[k - 1];
                cum += v;
                if (1.0f + (float)k * v > cum) { kz = k; cumkz = cum; }
            }
            float tau = (cumkz - 1.0f) / (float)kz;
            s_tau = tau;
            g_cnt[i] = kz;
            int lim = kz < 64 ? kz : 64;
            for (int k = 0; k < lim; k++) {
                g_sidx[i * 64 + k] = s_cidx[k];
                g_sval[i * 64 + k] = s_cval[k] - tau;
            }
        }
    }
    __syncthreads();                               // B3

    if (s_fb) {
        // fp32 Michelot fallback (safety only)
        float tau = -3.402823466e38f;
        for (int iter = 0; iter < 64; iter++) {
            float s = 0.f; int c = 0;
            #pragma unroll
            for (int it = 0; it < 8; it++) {
                float v = z[it];
                if (v > tau) { s += v; c++; }
            }
            #pragma unroll
            for (int o = 16; o; o >>= 1) {
                s += __shfl_xor_sync(0xffffffffu, s, o);
                c += __shfl_xor_sync(0xffffffffu, c, o);
            }
            if ((tid & 31) == 0) { wred[tid >> 5] = s; wcnt[tid >> 5] = c; }
            __syncthreads();
            if (tid == 0) {
                float S = 0.f; int C = 0;
                for (int w = 0; w < 16; w++) { S += wred[w]; C += wcnt[w]; }
                s_tau = (S - 1.0f) / (float)C;
            }
            __syncthreads();
            float tn = s_tau;
            if (tn == tau) break;
            tau = tn;
            __syncthreads();
        }
        if (tid == 0) g_cnt[i] = N;
        __syncthreads();
    }

    // pass C: direct coalesced scalar streaming stores from registers
    const float tau = s_tau;
    float* orow = outm + (size_t)i * N;
    #pragma unroll
    for (int it = 0; it < 8; it++) {
        __stcs(orow + tid + it * 512, fmaxf(z[it] - tau, 0.f));
    }
}

// ---------------- K2: symmetric bf16 Gram + exp + row/col partial sums ----------------
__device__ __forceinline__ void mma_bf16(float c[4], const unsigned a[4], const unsigned b[2]) {
    asm volatile(
        "mma.sync.aligned.m16n8k16.row.col.f32.bf16.bf16.f32 "
        "{%0,%1,%2,%3}, {%4,%5,%6,%7}, {%8,%9}, {%0,%1,%2,%3};\n"
        : "+f"(c[0]), "+f"(c[1]), "+f"(c[2]), "+f"(c[3])
        : "r"(a[0]), "r"(a[1]), "r"(a[2]), "r"(a[3]), "r"(b[0]), "r"(b[1]));
}

#define LDA 36

__global__ void __launch_bounds__(256) k_gemm() {
    int t = blockIdx.x, bi = 0;
    while (t >= 32 - bi) { t -= 32 - bi; bi++; }
    const int bj = bi + t;
    const bool diag = (bi == bj);

    __shared__ __align__(16) unsigned As[128 * LDA];
    __shared__ __align__(16) unsigned Bs[128 * LDA];
    __shared__ float sZr[128];
    __shared__ float sZc[4][128];

    const int tid = threadIdx.x;
    const int lane = tid & 31, wid = tid >> 5;
    const int wm = wid >> 1, wn = wid & 1;
    const int g = lane >> 2, t4 = lane & 3;

    if (tid < 128) sZr[tid] = 0.0f;

    float acc[2][8][4];
    #pragma unroll
    for (int mt = 0; mt < 2; mt++)
        #pragma unroll
        for (int nt = 0; nt < 8; nt++)
            #pragma unroll
            for (int k = 0; k < 4; k++) acc[mt][nt][k] = 0.0f;

    const int lr = tid >> 1;
    const int lh = tid & 1;
    const unsigned* Bp = diag ? As : Bs;

    // 2 k-chunks of 64 bf16 (= 32 packed uints) each
    for (int kc = 0; kc < 2; kc++) {
        #pragma unroll
        for (int q = 0; q < 4; q++) {
            int cv = lh * 4 + q;
            uint4 va = *(const uint4*)(g_fbf + ((size_t)(bi * 128 + lr) * 64 + kc * 32 + cv * 4));
            *(uint4*)(As + lr * LDA + cv * 4) = va;
            if (!diag) {
                uint4 vb = *(const uint4*)(g_fbf + ((size_t)(bj * 128 + lr) * 64 + kc * 32 + cv * 4));
                *(uint4*)(Bs + lr * LDA + cv * 4) = vb;
            }
        }
        __syncthreads();

        #pragma unroll
        for (int ks = 0; ks < 4; ks++) {
            unsigned a[2][4], b[8][2];
            #pragma unroll
            for (int mt = 0; mt < 2; mt++) {
                int r0 = wm * 32 + mt * 16 + g;
                a[mt][0] = As[r0 * LDA + ks * 8 + t4];
                a[mt][1] = As[(r0 + 8) * LDA + ks * 8 + t4];
                a[mt][2] = As[r0 * LDA + ks * 8 + t4 + 4];
                a[mt][3] = As[(r0 + 8) * LDA + ks * 8 + t4 + 4];
            }
            #pragma unroll
            for (int nt = 0; nt < 8; nt++) {
                int c0 = wn * 64 + nt * 8 + g;
                b[nt][0] = Bp[c0 * LDA + ks * 8 + t4];
                b[nt][1] = Bp[c0 * LDA + ks * 8 + t4 + 4];
            }
            #pragma unroll
            for (int mt = 0; mt < 2; mt++)
                #pragma unroll
                for (int nt = 0; nt < 8; nt++) mma_bf16(acc[mt][nt], a[mt], b[nt]);
        }
        __syncthreads();
    }

    const int ibase = bi * 128, jbase = bj * 128;
    float cp0[8], cp1[8];
    #pragma unroll
    for (int nt = 0; nt < 8; nt++) { cp0[nt] = 0.f; cp1[nt] = 0.f; }

    #pragma unroll
    for (int mt = 0; mt < 2; mt++) {
        int r0 = wm * 32 + mt * 16 + g;
        int gi0 = ibase + r0, gi1 = gi0 + 8;
        float rs0 = 0.f, rs1 = 0.f;
        #pragma unroll
        for (int nt = 0; nt < 8; nt++) {
            int c0 = wn * 64 + nt * 8 + t4 * 2;
            int gj0 = jbase + c0, gj1 = gj0 + 1;
            float e0 = __expf((acc[mt][nt][0] - 1.0f) * INV_T);
            float e1 = __expf((acc[mt][nt][1] - 1.0f) * INV_T);
            float e2 = __expf((acc[mt][nt][2] - 1.0f) * INV_T);
            float e3 = __expf((acc[mt][nt][3] - 1.0f) * INV_T);
            if (diag) {
                if (gj0 == gi0) e0 = 0.f;
                if (gj1 == gi0) e1 = 0.f;
                if (gj0 == gi1) e2 = 0.f;
                if (gj1 == gi1) e3 = 0.f;
            }
            rs0 += e0 + e1; rs1 += e2 + e3;
            cp0[nt] += e0 + e2; cp1[nt] += e1 + e3;
        }
        rs0 += __shfl_xor_sync(0xffffffffu, rs0, 1);
        rs0 += __shfl_xor_sync(0xffffffffu, rs0, 2);
        rs1 += __shfl_xor_sync(0xffffffffu, rs1, 1);
        rs1 += __shfl_xor_sync(0xffffffffu, rs1, 2);
        if (t4 == 0) {
            atomicAdd(&sZr[r0], rs0);
            atomicAdd(&sZr[r0 + 8], rs1);
        }
    }

    if (!diag) {
        #pragma unroll
        for (int nt = 0; nt < 8; nt++) {
            #pragma unroll
            for (int o = 4; o <= 16; o <<= 1) {
                cp0[nt] += __shfl_xor_sync(0xffffffffu, cp0[nt], o);
                cp1[nt] += __shfl_xor_sync(0xffffffffu, cp1[nt], o);
            }
        }
        if (g == 0) {
            #pragma unroll
            for (int nt = 0; nt < 8; nt++) {
                int c = wn * 64 + nt * 8 + t4 * 2;
                sZc[wm][c] = cp0[nt];
                sZc[wm][c + 1] = cp1[nt];
            }
        }
    }
    __syncthreads();

    if (tid < 128) {
        g_partial[(size_t)(ibase + tid) * 32 + bj] = sZr[tid];
        if (!diag) {
            float cs = ((sZc[0][tid] + sZc[1][tid]) + sZc[2][tid]) + sZc[3][tid];
            g_partial[(size_t)(jbase + tid) * 32 + bi] = cs;
        }
    }
}

// ---------------- K3: per-row log-prob (warp per row) + fused final loss ----------------
__global__ void __launch_bounds__(256) k_rowfix(const float* __restrict__ outm,
                                                float* __restrict__ out, int moff) {
    const int wid = threadIdx.x >> 5, lane = threadIdx.x & 31;
    const int i = blockIdx.x * 8 + wid;

    const float4 a = *(const float4*)(g_f + (size_t)i * D + lane * 4);

    auto dot = [&](int j) -> float {
        float4 b = *(const float4*)(g_f + (size_t)j * D + lane * 4);
        float p = a.x * b.x + a.y * b.y + a.z * b.z + a.w * b.w;
        #pragma unroll
        for (int o = 16; o; o >>= 1) p += __shfl_xor_sync(0xffffffffu, p, o);
        return p;
    };

    // corr must match gemm's bf16-level sim so Z - corr is consistent
    auto dotbf = [&](int j) -> float {
        uint2 pa = *(const uint2*)(g_fbf + (size_t)i * 64 + lane * 2);
        uint2 pb = *(const uint2*)(g_fbf + (size_t)j * 64 + lane * 2);
        float ax0 = __uint_as_float(pa.x << 16), ax1 = __uint_as_float(pa.x & 0xffff0000u);
        float ay0 = __uint_as_float(pa.y << 16), ay1 = __uint_as_float(pa.y & 0xffff0000u);
        float bx0 = __uint_as_float(pb.x << 16), bx1 = __uint_as_float(pb.x & 0xffff0000u);
        float by0 = __uint_as_float(pb.y << 16), by1 = __uint_as_float(pb.y & 0xffff0000u);
        float p = ax0 * bx0 + ax1 * bx1 + ay0 * by0 + ay1 * by1;
        #pragma unroll
        for (int o = 16; o; o >>= 1) p += __shfl_xor_sync(0xffffffffu, p, o);
        return p;
    };

    float simpos = (dot(i ^ BHALF) - 1.0f) * INV_T;

    int cnt = g_cnt[i];
    float corr = 0.0f;
    if (cnt <= 64) {
        for (int k = 0; k < cnt; k++) {
            int j = g_sidx[i * 64 + k];
            float m = g_sval[i * 64 + k];
            corr += m * __expf((dotbf(j) - 1.0f) * INV_T);
        }
    } else {
        for (int j = 0; j < N; j++) {
            float m = outm[(size_t)i * N + j];
            if (m > 0.0f) corr += m * __expf((dotbf(j) - 1.0f) * INV_T);
        }
    }

    float zp = g_partial[(size_t)i * 32 + lane];   // one coalesced 128B line per warp
    #pragma unroll
    for (int o = 16; o; o >>= 1) zp += __shfl_xor_sync(0xffffffffu, zp, o);

    if (lane == 0) g_lp[i] = simpos - logf(zp - corr);

    // ---- last-block loss reduction (threadFenceReduction pattern; deterministic order) ----
    __syncthreads();
    __shared__ bool isLast;
    if (threadIdx.x == 0) {
        __threadfence();
        int prev = atomicAdd(&g_done, 1);
        isLast = (prev == (int)gridDim.x - 1);
    }
    __syncthreads();
    if (isLast) {
        __shared__ float sm[8];
        float s = 0.0f;
        #pragma unroll
        for (int k = 0; k < 16; k++) s += g_lp[threadIdx.x + k * 256];
        #pragma unroll
        for (int o = 16; o; o >>= 1) s += __shfl_xor_sync(0xffffffffu, s, o);
        if (lane == 0) sm[wid] = s;
        __syncthreads();
        if (threadIdx.x == 0) {
            float tot = ((sm[0] + sm[1]) + (sm[2] + sm[3])) + ((sm[4] + sm[5]) + (sm[6] + sm[7]));
            float loss = -(tot / 4096.0f);
            for (int q = 0; q < moff; q++) out[q] = loss;
            g_done = 0;   // reset for next graph replay
        }
    }
}

// ---------------- launch ----------------
extern "C" void kernel_launch(void* const* d_in, const int* in_sizes, int n_in,
                              void* d_out, int out_size) {
    int fidx = (in_sizes[0] == N * D) ? 0 : 1;
    const float* feat = (const float*)d_in[fidx];
    const float* attn = (const float*)d_in[1 - fidx];
    float* out = (float*)d_out;

    long long nn = (long long)N * (long long)N;
    int moff = (int)((long long)out_size - nn);
    if (moff < 0) moff = 0;
    float* outm = out + moff;

    k_sparse<<<N, 512>>>(feat, attn, outm);
    k_gemm<<<528, 256>>>();
    k_rowfix<<<512, 256>>>(outm, out, moff);
}

// round 13
// speedup vs baseline: 1.4458x; 1.0711x over previous
#include <cuda_runtime.h>
#include <cstdint>

#define N 4096
#define D 128
#define BHALF 2048
#define INV_T 14.285714285714285714f  /* 1/0.07 */

// ---------------- scratch (static device globals; no allocation) ----------------
__device__ __align__(16) float    g_f[N * D];      // L2-normalized features, fp32
__device__ __align__(16) unsigned g_fbf[N * 64];   // packed bf16x2 (64 uints per row)
__device__ int    g_cnt[N];
__device__ int    g_sidx[N * 64];
__device__ float  g_sval[N * 64];
__device__ float  g_partial[N * 32];               // [row][slot] coalesced for rowfix
__device__ float  g_lp[N];
__device__ int    g_done;                          // zero-init; reset by last block each call

// ---------------- K1: fused L2-norm (warp 0) + row-wise sparsemax ----------------
#define CAND_MAX 128

__global__ void __launch_bounds__(512, 4) k_sparse(const float* __restrict__ feat,
                                                   const float* __restrict__ attn,
                                                   float* __restrict__ outm) {
    const int i = blockIdx.x;
    const int tid = threadIdx.x;
    __shared__ float wred[16];
    __shared__ int   wcnt[16];
    __shared__ float s_tau;
    __shared__ int   s_ccnt, s_fb;
    __shared__ int   s_cidx[CAND_MAX];
    __shared__ float s_cval[CAND_MAX];

    // norm prologue: warp 0 normalizes feature row i (fp32 + packed bf16 copies)
    if (tid < 32) {
        float4 v = *(const float4*)(feat + (size_t)i * D + tid * 4);
        float s = v.x * v.x + v.y * v.y + v.z * v.z + v.w * v.w;
        #pragma unroll
        for (int o = 16; o; o >>= 1) s += __shfl_xor_sync(0xffffffffu, s, o);
        float r = sqrtf(s);
        float4 f = make_float4(v.x / r, v.y / r, v.z / r, v.w / r);
        *(float4*)(g_f + (size_t)i * D + tid * 4) = f;
        unsigned p0, p1;
        asm("cvt.rn.bf16x2.f32 %0, %1, %2;" : "=r"(p0) : "f"(f.y), "f"(f.x));
        asm("cvt.rn.bf16x2.f32 %0, %1, %2;" : "=r"(p1) : "f"(f.w), "f"(f.z));
        *(uint2*)(g_fbf + (size_t)i * 64 + tid * 2) = make_uint2(p0, p1);
    }

    const int j1 = i & (BHALF - 1);        // in [0, 2048)
    const int j2 = j1 + BHALF;             // in [2048, 4096)
    const float* row = attn + (size_t)i * N;
    float* orow = outm + (size_t)i * N;

    // pass A: coalesced scalar streaming loads (register resident), mask, warp max
    float z[8];
    float mx = -3.402823466e38f;
    #pragma unroll
    for (int it = 0; it < 8; it++) {
        int j = tid + it * 512;
        float v = __ldcs(row + j) * INV_T;
        if (it < 4) { if (j == j1) v = 0.f; }
        else        { if (j == j2) v = 0.f; }
        z[it] = v;
        mx = fmaxf(mx, v);
    }

    // zero-fill pass (independent of loads): masked row is 0 except the support.
    // vectorized STG.128 with dynamic alignment (outm may be only 4B-aligned).
    {
        const int jstart = (4 - (((unsigned)(size_t)orow >> 2) & 3)) & 3;
        const int nvec = (N - jstart) >> 2;
        const int tail = N - jstart - (nvec << 2);
        if (tid < jstart) __stcs(orow + tid, 0.f);
        if (tid >= 4 && tid < 4 + tail) __stcs(orow + N - 1 - (tid - 4), 0.f);
        float4* ov = (float4*)(orow + jstart);
        const float4 zq = make_float4(0.f, 0.f, 0.f, 0.f);
        for (int it = tid; it < nvec; it += 512) __stcs(ov + it, zq);
    }

    #pragma unroll
    for (int o = 16; o; o >>= 1) mx = fmaxf(mx, __shfl_xor_sync(0xffffffffu, mx, o));
    if ((tid & 31) == 0) wred[tid >> 5] = mx;
    if (tid == 0) s_ccnt = 0;
    __syncthreads();                               // B1

    // every thread reduces the 16 warp maxima itself (broadcast LDS)
    float bm = wred[0];
    #pragma unroll
    for (int w = 1; w < 16; w++) bm = fmaxf(bm, wred[w]);
    const float thr = bm - 1.0f;                   // sparsemax support bound: tau >= max-1

    // pass B: gather candidates z >= thr
    #pragma unroll
    for (int it = 0; it < 8; it++) {
        float v = z[it];
        if (v >= thr) {
            int p = atomicAdd(&s_ccnt, 1);
            if (p < CAND_MAX) { s_cidx[p] = tid + it * 512; s_cval[p] = v; }
        }
    }
    __syncthreads();                               // B2 (also orders zero-stores before support writes)

    if (tid == 0) {
        int cnt = s_ccnt;
        s_fb = (cnt > CAND_MAX);
        if (!s_fb) {
            // insertion sort desc by (value, index asc) -> deterministic
            for (int a = 1; a < cnt; a++) {
                float v = s_cval[a]; int ix = s_cidx[a];
                int b = a - 1;
                while (b >= 0 && (s_cval[b] < v || (s_cval[b] == v && s_cidx[b] > ix))) {
                    s_cval[b + 1] = s_cval[b]; s_cidx[b + 1] = s_cidx[b]; b--;
                }
                s_cval[b + 1] = v; s_cidx[b + 1] = ix;
            }
            // reference formula: fp32 sequential cumsum over descending values
            float cum = 0.f, cumkz = 1.f; int kz = 1;
            for (int k = 1; k <= cnt; k++) {
                float v = s_cval[k - 1];
                cum += v;
                if (1.0f + (float)k * v > cum) { kz = k; cumkz = cum; }
            }
            float tau = (cumkz - 1.0f) / (float)kz;
            s_tau = tau;
            g_cnt[i] = kz;
            int lim = kz < 64 ? kz : 64;
            for (int k = 0; k < lim; k++) {
                g_sidx[i * 64 + k] = s_cidx[k];
                g_sval[i * 64 + k] = s_cval[k] - tau;
            }
            // support entries are the only nonzeros of the masked row
            for (int k = 0; k < kz; k++) {
                orow[s_cidx[k]] = s_cval[k] - tau;
            }
        }
    }
    __syncthreads();                               // B3

    if (s_fb) {
        // fp32 Michelot fallback (safety only): full-row recompute + scalar stores
        float tau = -3.402823466e38f;
        for (int iter = 0; iter < 64; iter++) {
            float s = 0.f; int c = 0;
            #pragma unroll
            for (int it = 0; it < 8; it++) {
                float v = z[it];
                if (v > tau) { s += v; c++; }
            }
            #pragma unroll
            for (int o = 16; o; o >>= 1) {
                s += __shfl_xor_sync(0xffffffffu, s, o);
                c += __shfl_xor_sync(0xffffffffu, c, o);
            }
            if ((tid & 31) == 0) { wred[tid >> 5] = s; wcnt[tid >> 5] = c; }
            __syncthreads();
            if (tid == 0) {
                float S = 0.f; int C = 0;
                for (int w = 0; w < 16; w++) { S += wred[w]; C += wcnt[w]; }
                s_tau = (S - 1.0f) / (float)C;
            }
            __syncthreads();
            float tn = s_tau;
            if (tn == tau) break;
            tau = tn;
            __syncthreads();
        }
        if (tid == 0) g_cnt[i] = N;
        __syncthreads();
        const float tauf = s_tau;
        #pragma unroll
        for (int it = 0; it < 8; it++) {
            orow[tid + it * 512] = fmaxf(z[it] - tauf, 0.f);
        }
    }
}

// ---------------- K2: symmetric bf16 Gram + exp + row/col partial sums ----------------
__device__ __forceinline__ void mma_bf16(float c[4], const unsigned a[4], const unsigned b[2]) {
    asm volatile(
        "mma.sync.aligned.m16n8k16.row.col.f32.bf16.bf16.f32 "
        "{%0,%1,%2,%3}, {%4,%5,%6,%7}, {%8,%9}, {%0,%1,%2,%3};\n"
        : "+f"(c[0]), "+f"(c[1]), "+f"(c[2]), "+f"(c[3])
        : "r"(a[0]), "r"(a[1]), "r"(a[2]), "r"(a[3]), "r"(b[0]), "r"(b[1]));
}

#define LDA 36

__global__ void __launch_bounds__(256) k_gemm() {
    int t = blockIdx.x, bi = 0;
    while (t >= 32 - bi) { t -= 32 - bi; bi++; }
    const int bj = bi + t;
    const bool diag = (bi == bj);

    __shared__ __align__(16) unsigned As[128 * LDA];
    __shared__ __align__(16) unsigned Bs[128 * LDA];
    __shared__ float sZr[128];
    __shared__ float sZc[4][128];

    const int tid = threadIdx.x;
    const int lane = tid & 31, wid = tid >> 5;
    const int wm = wid >> 1, wn = wid & 1;
    const int g = lane >> 2, t4 = lane & 3;

    if (tid < 128) sZr[tid] = 0.0f;

    float acc[2][8][4];
    #pragma unroll
    for (int mt = 0; mt < 2; mt++)
        #pragma unroll
        for (int nt = 0; nt < 8; nt++)
            #pragma unroll
            for (int k = 0; k < 4; k++) acc[mt][nt][k] = 0.0f;

    const int lr = tid >> 1;
    const int lh = tid & 1;
    const unsigned* Bp = diag ? As : Bs;

    // 2 k-chunks of 64 bf16 (= 32 packed uints) each
    for (int kc = 0; kc < 2; kc++) {
        #pragma unroll
        for (int q = 0; q < 4; q++) {
            int cv = lh * 4 + q;
            uint4 va = *(const uint4*)(g_fbf + ((size_t)(bi * 128 + lr) * 64 + kc * 32 + cv * 4));
            *(uint4*)(As + lr * LDA + cv * 4) = va;
            if (!diag) {
                uint4 vb = *(const uint4*)(g_fbf + ((size_t)(bj * 128 + lr) * 64 + kc * 32 + cv * 4));
                *(uint4*)(Bs + lr * LDA + cv * 4) = vb;
            }
        }
        __syncthreads();

        #pragma unroll
        for (int ks = 0; ks < 4; ks++) {
            unsigned a[2][4], b[8][2];
            #pragma unroll
            for (int mt = 0; mt < 2; mt++) {
                int r0 = wm * 32 + mt * 16 + g;
                a[mt][0] = As[r0 * LDA + ks * 8 + t4];
                a[mt][1] = As[(r0 + 8) * LDA + ks * 8 + t4];
                a[mt][2] = As[r0 * LDA + ks * 8 + t4 + 4];
                a[mt][3] = As[(r0 + 8) * LDA + ks * 8 + t4 + 4];
            }
            #pragma unroll
            for (int nt = 0; nt < 8; nt++) {
                int c0 = wn * 64 + nt * 8 + g;
                b[nt][0] = Bp[c0 * LDA + ks * 8 + t4];
                b[nt][1] = Bp[c0 * LDA + ks * 8 + t4 + 4];
            }
            #pragma unroll
            for (int mt = 0; mt < 2; mt++)
                #pragma unroll
                for (int nt = 0; nt < 8; nt++) mma_bf16(acc[mt][nt], a[mt], b[nt]);
        }
        __syncthreads();
    }

    const int ibase = bi * 128, jbase = bj * 128;
    float cp0[8], cp1[8];
    #pragma unroll
    for (int nt = 0; nt < 8; nt++) { cp0[nt] = 0.f; cp1[nt] = 0.f; }

    #pragma unroll
    for (int mt = 0; mt < 2; mt++) {
        int r0 = wm * 32 + mt * 16 + g;
        int gi0 = ibase + r0, gi1 = gi0 + 8;
        float rs0 = 0.f, rs1 = 0.f;
        #pragma unroll
        for (int nt = 0; nt < 8; nt++) {
            int c0 = wn * 64 + nt * 8 + t4 * 2;
            int gj0 = jbase + c0, gj1 = gj0 + 1;
            float e0 = __expf((acc[mt][nt][0] - 1.0f) * INV_T);
            float e1 = __expf((acc[mt][nt][1] - 1.0f) * INV_T);
            float e2 = __expf((acc[mt][nt][2] - 1.0f) * INV_T);
            float e3 = __expf((acc[mt][nt][3] - 1.0f) * INV_T);
            if (diag) {
                if (gj0 == gi0) e0 = 0.f;
                if (gj1 == gi0) e1 = 0.f;
                if (gj0 == gi1) e2 = 0.f;
                if (gj1 == gi1) e3 = 0.f;
            }
            rs0 += e0 + e1; rs1 += e2 + e3;
            cp0[nt] += e0 + e2; cp1[nt] += e1 + e3;
        }
        rs0 += __shfl_xor_sync(0xffffffffu, rs0, 1);
        rs0 += __shfl_xor_sync(0xffffffffu, rs0, 2);
        rs1 += __shfl_xor_sync(0xffffffffu, rs1, 1);
        rs1 += __shfl_xor_sync(0xffffffffu, rs1, 2);
        if (t4 == 0) {
            atomicAdd(&sZr[r0], rs0);
            atomicAdd(&sZr[r0 + 8], rs1);
        }
    }

    if (!diag) {
        #pragma unroll
        for (int nt = 0; nt < 8; nt++) {
            #pragma unroll
            for (int o = 4; o <= 16; o <<= 1) {
                cp0[nt] += __shfl_xor_sync(0xffffffffu, cp0[nt], o);
                cp1[nt] += __shfl_xor_sync(0xffffffffu, cp1[nt], o);
            }
        }
        if (g == 0) {
            #pragma unroll
            for (int nt = 0; nt < 8; nt++) {
                int c = wn * 64 + nt * 8 + t4 * 2;
                sZc[wm][c] = cp0[nt];
                sZc[wm][c + 1] = cp1[nt];
            }
        }
    }
    __syncthreads();

    if (tid < 128) {
        g_partial[(size_t)(ibase + tid) * 32 + bj] = sZr[tid];
        if (!diag) {
            float cs = ((sZc[0][tid] + sZc[1][tid]) + sZc[2][tid]) + sZc[3][tid];
            g_partial[(size_t)(jbase + tid) * 32 + bi] = cs;
        }
    }
}

// ---------------- K3: per-row log-prob (warp per row) + fused final loss ----------------
__global__ void __launch_bounds__(256) k_rowfix(const float* __restrict__ outm,
                                                float* __restrict__ out, int moff) {
    const int wid = threadIdx.x >> 5, lane = threadIdx.x & 31;
    const int i = blockIdx.x * 8 + wid;

    const float4 a = *(const float4*)(g_f + (size_t)i * D + lane * 4);

    auto dot = [&](int j) -> float {
        float4 b = *(const float4*)(g_f + (size_t)j * D + lane * 4);
        float p = a.x * b.x + a.y * b.y + a.z * b.z + a.w * b.w;
        #pragma unroll
        for (int o = 16; o; o >>= 1) p += __shfl_xor_sync(0xffffffffu, p, o);
        return p;
    };

    // corr must match gemm's bf16-level sim so Z - corr is consistent
    auto dotbf = [&](int j) -> float {
        uint2 pa = *(const uint2*)(g_fbf + (size_t)i * 64 + lane * 2);
        uint2 pb = *(const uint2*)(g_fbf + (size_t)j * 64 + lane * 2);
        float ax0 = __uint_as_float(pa.x << 16), ax1 = __uint_as_float(pa.x & 0xffff0000u);
        float ay0 = __uint_as_float(pa.y << 16), ay1 = __uint_as_float(pa.y & 0xffff0000u);
        float bx0 = __uint_as_float(pb.x << 16), bx1 = __uint_as_float(pb.x & 0xffff0000u);
        float by0 = __uint_as_float(pb.y << 16), by1 = __uint_as_float(pb.y & 0xffff0000u);
        float p = ax0 * bx0 + ax1 * bx1 + ay0 * by0 + ay1 * by1;
        #pragma unroll
        for (int o = 16; o; o >>= 1) p += __shfl_xor_sync(0xffffffffu, p, o);
        return p;
    };

    float simpos = (dot(i ^ BHALF) - 1.0f) * INV_T;

    int cnt = g_cnt[i];
    float corr = 0.0f;
    if (cnt <= 64) {
        for (int k = 0; k < cnt; k++) {
            int j = g_sidx[i * 64 + k];
            float m = g_sval[i * 64 + k];
            corr += m * __expf((dotbf(j) - 1.0f) * INV_T);
        }
    } else {
        for (int j = 0; j < N; j++) {
            float m = outm[(size_t)i * N + j];
            if (m > 0.0f) corr += m * __expf((dotbf(j) - 1.0f) * INV_T);
        }
    }

    float zp = g_partial[(size_t)i * 32 + lane];   // one coalesced 128B line per warp
    #pragma unroll
    for (int o = 16; o; o >>= 1) zp += __shfl_xor_sync(0xffffffffu, zp, o);

    if (lane == 0) g_lp[i] = simpos - logf(zp - corr);

    // ---- last-block loss reduction (threadFenceReduction pattern; deterministic order) ----
    __syncthreads();
    __shared__ bool isLast;
    if (threadIdx.x == 0) {
        __threadfence();
        int prev = atomicAdd(&g_done, 1);
        isLast = (prev == (int)gridDim.x - 1);
    }
    __syncthreads();
    if (isLast) {
        __shared__ float sm[8];
        float s = 0.0f;
        #pragma unroll
        for (int k = 0; k < 16; k++) s += g_lp[threadIdx.x + k * 256];
        #pragma unroll
        for (int o = 16; o; o >>= 1) s += __shfl_xor_sync(0xffffffffu, s, o);
        if (lane == 0) sm[wid] = s;
        __syncthreads();
        if (threadIdx.x == 0) {
            float tot = ((sm[0] + sm[1]) + (sm[2] + sm[3])) + ((sm[4] + sm[5]) + (sm[6] + sm[7]));
            float loss = -(tot / 4096.0f);
            for (int q = 0; q < moff; q++) out[q] = loss;
            g_done = 0;   // reset for next graph replay
        }
    }
}

// ---------------- launch ----------------
extern "C" void kernel_launch(void* const* d_in, const int* in_sizes, int n_in,
                              void* d_out, int out_size) {
    int fidx = (in_sizes[0] == N * D) ? 0 : 1;
    const float* feat = (const float*)d_in[fidx];
    const float* attn = (const float*)d_in[1 - fidx];
    float* out = (float*)d_out;

    long long nn = (long long)N * (long long)N;
    int moff = (int)((long long)out_size - nn);
    if (moff < 0) moff = 0;
    float* outm = out + moff;

    k_sparse<<<N, 512>>>(feat, attn, outm);
    k_gemm<<<528, 256>>>();
    k_rowfix<<<512, 256>>>(outm, out, moff);
}

// round 14
// speedup vs baseline: 1.4945x; 1.0337x over previous
#include <cuda_runtime.h>
#include <cstdint>

#define N 4096
#define D 128
#define BHALF 2048
#define INV_T 14.285714285714285714f  /* 1/0.07 */

// ---------------- scratch (static device globals; no allocation) ----------------
__device__ __align__(16) float    g_f[N * D];      // L2-normalized features, fp32
__device__ __align__(16) unsigned g_fbf[N * 64];   // packed bf16x2 (64 uints per row)
__device__ int    g_cnt[N];
__device__ int    g_sidx[N * 64];
__device__ float  g_sval[N * 64];
__device__ float  g_partial[N * 32];               // [row][slot] coalesced for rowfix
__device__ float  g_lp[N];
__device__ int    g_done;                          // zero-init; reset by last block each call

// ---------------- K1: fused L2-norm (warp 0) + row-wise sparsemax ----------------
#define CAND_MAX 128

__global__ void __launch_bounds__(512, 4) k_sparse(const float* __restrict__ feat,
                                                   const float* __restrict__ attn,
                                                   float* __restrict__ outm) {
    const int i = blockIdx.x;
    const int tid = threadIdx.x;
    __shared__ float wred[16];
    __shared__ int   wcnt[16];
    __shared__ float s_tau;
    __shared__ int   s_ccnt, s_fb;
    __shared__ int   s_cidx[CAND_MAX];
    __shared__ float s_cval[CAND_MAX];

    // norm prologue: warp 0 normalizes feature row i (fp32 + packed bf16 copies)
    if (tid < 32) {
        float4 v = *(const float4*)(feat + (size_t)i * D + tid * 4);
        float s = v.x * v.x + v.y * v.y + v.z * v.z + v.w * v.w;
        #pragma unroll
        for (int o = 16; o; o >>= 1) s += __shfl_xor_sync(0xffffffffu, s, o);
        float r = sqrtf(s);
        float4 f = make_float4(v.x / r, v.y / r, v.z / r, v.w / r);
        *(float4*)(g_f + (size_t)i * D + tid * 4) = f;
        unsigned p0, p1;
        asm("cvt.rn.bf16x2.f32 %0, %1, %2;" : "=r"(p0) : "f"(f.y), "f"(f.x));
        asm("cvt.rn.bf16x2.f32 %0, %1, %2;" : "=r"(p1) : "f"(f.w), "f"(f.z));
        *(uint2*)(g_fbf + (size_t)i * 64 + tid * 2) = make_uint2(p0, p1);
    }

    const int j1 = i & (BHALF - 1);        // in [0, 2048)
    const int j2 = j1 + BHALF;             // in [2048, 4096)
    const float4* row4 = (const float4*)(attn + (size_t)i * N);
    float* orow = outm + (size_t)i * N;

    // pass A: two LDG.128 per thread; z[0..3] = elements 4*tid.., z[4..7] = 2048+4*tid..
    float z[8];
    {
        float4 r0 = __ldcs(row4 + tid);
        float4 r1 = __ldcs(row4 + tid + 512);
        z[0] = r0.x * INV_T; z[1] = r0.y * INV_T; z[2] = r0.z * INV_T; z[3] = r0.w * INV_T;
        z[4] = r1.x * INV_T; z[5] = r1.y * INV_T; z[6] = r1.z * INV_T; z[7] = r1.w * INV_T;
        // both positives live in the SAME thread: j2>>2 - 512 == j1>>2
        if (tid == (j1 >> 2)) {
            int q = j1 & 3;
            z[q] = 0.f;          // q is compile-unknowable but range [0,4): becomes 4 predicated SELs in one rare branch
            z[4 + q] = 0.f;
        }
    }

    // zero-fill pass (independent of loads): masked row is 0 except the support.
    {
        const int jstart = (4 - (((unsigned)(size_t)orow >> 2) & 3)) & 3;
        const int nvec = (N - jstart) >> 2;
        const int tail = N - jstart - (nvec << 2);
        if (tid < jstart) __stcs(orow + tid, 0.f);
        if (tid >= 4 && tid < 4 + tail) __stcs(orow + N - 1 - (tid - 4), 0.f);
        float4* ov = (float4*)(orow + jstart);
        const float4 zq = make_float4(0.f, 0.f, 0.f, 0.f);
        for (int it = tid; it < nvec; it += 512) __stcs(ov + it, zq);
    }

    float mx = fmaxf(fmaxf(fmaxf(z[0], z[1]), fmaxf(z[2], z[3])),
                     fmaxf(fmaxf(z[4], z[5]), fmaxf(z[6], z[7])));
    #pragma unroll
    for (int o = 16; o; o >>= 1) mx = fmaxf(mx, __shfl_xor_sync(0xffffffffu, mx, o));
    if ((tid & 31) == 0) wred[tid >> 5] = mx;
    if (tid == 0) s_ccnt = 0;
    __syncthreads();                               // B1

    // every thread reduces the 16 warp maxima itself (broadcast LDS)
    float bm = wred[0];
    #pragma unroll
    for (int w = 1; w < 16; w++) bm = fmaxf(bm, wred[w]);
    const float thr = bm - 1.0f;                   // sparsemax support bound: tau >= max-1

    // pass B: gather candidates z >= thr (element index per float4 layout)
    #pragma unroll
    for (int it = 0; it < 8; it++) {
        float v = z[it];
        if (v >= thr) {
            int j = (it < 4) ? (tid * 4 + it) : (2048 + tid * 4 + (it - 4));
            int p = atomicAdd(&s_ccnt, 1);
            if (p < CAND_MAX) { s_cidx[p] = j; s_cval[p] = v; }
        }
    }
    __syncthreads();                               // B2 (also orders zero-stores before support writes)

    if (tid == 0) {
        int cnt = s_ccnt;
        s_fb = (cnt > CAND_MAX);
        if (!s_fb) {
            // insertion sort desc by (value, index asc) -> deterministic
            for (int a = 1; a < cnt; a++) {
                float v = s_cval[a]; int ix = s_cidx[a];
                int b = a - 1;
                while (b >= 0 && (s_cval[b] < v || (s_cval[b] == v && s_cidx[b] > ix))) {
                    s_cval[b + 1] = s_cval[b]; s_cidx[b + 1] = s_cidx[b]; b--;
                }
                s_cval[b + 1] = v; s_cidx[b + 1] = ix;
            }
            // reference formula: fp32 sequential cumsum over descending values
            float cum = 0.f, cumkz = 1.f; int kz = 1;
            for (int k = 1; k <= cnt; k++) {
                float v = s_cval[k - 1];
                cum += v;
                if (1.0f + (float)k * v > cum) { kz = k; cumkz = cum; }
            }
            float tau = (cumkz - 1.0f) / (float)kz;
            s_tau = tau;
            g_cnt[i] = kz;
            int lim = kz < 64 ? kz : 64;
            for (int k = 0; k < lim; k++) {
                g_sidx[i * 64 + k] = s_cidx[k];
                g_sval[i * 64 + k] = s_cval[k] - tau;
            }
            // support entries are the only nonzeros of the masked row
            for (int k = 0; k < kz; k++) {
                orow[s_cidx[k]] = s_cval[k] - tau;
            }
        }
    }
    __syncthreads();                               // B3

    if (s_fb) {
        // fp32 Michelot fallback (safety only): full-row recompute + scalar stores
        float tau = -3.402823466e38f;
        for (int iter = 0; iter < 64; iter++) {
            float s = 0.f; int c = 0;
            #pragma unroll
            for (int it = 0; it < 8; it++) {
                float v = z[it];
                if (v > tau) { s += v; c++; }
            }
            #pragma unroll
            for (int o = 16; o; o >>= 1) {
                s += __shfl_xor_sync(0xffffffffu, s, o);
                c += __shfl_xor_sync(0xffffffffu, c, o);
            }
            if ((tid & 31) == 0) { wred[tid >> 5] = s; wcnt[tid >> 5] = c; }
            __syncthreads();
            if (tid == 0) {
                float S = 0.f; int C = 0;
                for (int w = 0; w < 16; w++) { S += wred[w]; C += wcnt[w]; }
                s_tau = (S - 1.0f) / (float)C;
            }
            __syncthreads();
            float tn = s_tau;
            if (tn == tau) break;
            tau = tn;
            __syncthreads();
        }
        if (tid == 0) g_cnt[i] = N;
        __syncthreads();
        const float tauf = s_tau;
        #pragma unroll
        for (int it = 0; it < 4; it++) orow[tid * 4 + it] = fmaxf(z[it] - tauf, 0.f);
        #pragma unroll
        for (int it = 0; it < 4; it++) orow[2048 + tid * 4 + it] = fmaxf(z[4 + it] - tauf, 0.f);
    }
}

// ---------------- K2: symmetric bf16 Gram + exp + row/col partial sums ----------------
__device__ __forceinline__ void mma_bf16(float c[4], const unsigned a[4], const unsigned b[2]) {
    asm volatile(
        "mma.sync.aligned.m16n8k16.row.col.f32.bf16.bf16.f32 "
        "{%0,%1,%2,%3}, {%4,%5,%6,%7}, {%8,%9}, {%0,%1,%2,%3};\n"
        : "+f"(c[0]), "+f"(c[1]), "+f"(c[2]), "+f"(c[3])
        : "r"(a[0]), "r"(a[1]), "r"(a[2]), "r"(a[3]), "r"(b[0]), "r"(b[1]));
}

#define LDA 36

__global__ void __launch_bounds__(256) k_gemm() {
    int t = blockIdx.x, bi = 0;
    while (t >= 32 - bi) { t -= 32 - bi; bi++; }
    const int bj = bi + t;
    const bool diag = (bi == bj);

    __shared__ __align__(16) unsigned As[128 * LDA];
    __shared__ __align__(16) unsigned Bs[128 * LDA];
    __shared__ float sZr[128];
    __shared__ float sZc[4][128];

    const int tid = threadIdx.x;
    const int lane = tid & 31, wid = tid >> 5;
    const int wm = wid >> 1, wn = wid & 1;
    const int g = lane >> 2, t4 = lane & 3;

    if (tid < 128) sZr[tid] = 0.0f;

    float acc[2][8][4];
    #pragma unroll
    for (int mt = 0; mt < 2; mt++)
        #pragma unroll
        for (int nt = 0; nt < 8; nt++)
            #pragma unroll
            for (int k = 0; k < 4; k++) acc[mt][nt][k] = 0.0f;

    const int lr = tid >> 1;
    const int lh = tid & 1;
    const unsigned* Bp = diag ? As : Bs;

    // 2 k-chunks of 64 bf16 (= 32 packed uints) each
    for (int kc = 0; kc < 2; kc++) {
        #pragma unroll
        for (int q = 0; q < 4; q++) {
            int cv = lh * 4 + q;
            uint4 va = *(const uint4*)(g_fbf + ((size_t)(bi * 128 + lr) * 64 + kc * 32 + cv * 4));
            *(uint4*)(As + lr * LDA + cv * 4) = va;
            if (!diag) {
                uint4 vb = *(const uint4*)(g_fbf + ((size_t)(bj * 128 + lr) * 64 + kc * 32 + cv * 4));
                *(uint4*)(Bs + lr * LDA + cv * 4) = vb;
            }
        }
        __syncthreads();

        #pragma unroll
        for (int ks = 0; ks < 4; ks++) {
            unsigned a[2][4], b[8][2];
            #pragma unroll
            for (int mt = 0; mt < 2; mt++) {
                int r0 = wm * 32 + mt * 16 + g;
                a[mt][0] = As[r0 * LDA + ks * 8 + t4];
                a[mt][1] = As[(r0 + 8) * LDA + ks * 8 + t4];
                a[mt][2] = As[r0 * LDA + ks * 8 + t4 + 4];
                a[mt][3] = As[(r0 + 8) * LDA + ks * 8 + t4 + 4];
            }
            #pragma unroll
            for (int nt = 0; nt < 8; nt++) {
                int c0 = wn * 64 + nt * 8 + g;
                b[nt][0] = Bp[c0 * LDA + ks * 8 + t4];
                b[nt][1] = Bp[c0 * LDA + ks * 8 + t4 + 4];
            }
            #pragma unroll
            for (int mt = 0; mt < 2; mt++)
                #pragma unroll
                for (int nt = 0; nt < 8; nt++) mma_bf16(acc[mt][nt], a[mt], b[nt]);
        }
        __syncthreads();
    }

    const int ibase = bi * 128, jbase = bj * 128;
    float cp0[8], cp1[8];
    #pragma unroll
    for (int nt = 0; nt < 8; nt++) { cp0[nt] = 0.f; cp1[nt] = 0.f; }

    #pragma unroll
    for (int mt = 0; mt < 2; mt++) {
        int r0 = wm * 32 + mt * 16 + g;
        int gi0 = ibase + r0, gi1 = gi0 + 8;
        float rs0 = 0.f, rs1 = 0.f;
        #pragma unroll
        for (int nt = 0; nt < 8; nt++) {
            int c0 = wn * 64 + nt * 8 + t4 * 2;
            int gj0 = jbase + c0, gj1 = gj0 + 1;
            float e0 = __expf((acc[mt][nt][0] - 1.0f) * INV_T);
            float e1 = __expf((acc[mt][nt][1] - 1.0f) * INV_T);
            float e2 = __expf((acc[mt][nt][2] - 1.0f) * INV_T);
            float e3 = __expf((acc[mt][nt][3] - 1.0f) * INV_T);
            if (diag) {
                if (gj0 == gi0) e0 = 0.f;
                if (gj1 == gi0) e1 = 0.f;
                if (gj0 == gi1) e2 = 0.f;
                if (gj1 == gi1) e3 = 0.f;
            }
            rs0 += e0 + e1; rs1 += e2 + e3;
            cp0[nt] += e0 + e2; cp1[nt] += e1 + e3;
        }
        rs0 += __shfl_xor_sync(0xffffffffu, rs0, 1);
        rs0 += __shfl_xor_sync(0xffffffffu, rs0, 2);
        rs1 += __shfl_xor_sync(0xffffffffu, rs1, 1);
        rs1 += __shfl_xor_sync(0xffffffffu, rs1, 2);
        if (t4 == 0) {
            atomicAdd(&sZr[r0], rs0);
            atomicAdd(&sZr[r0 + 8], rs1);
        }
    }

    if (!diag) {
        #pragma unroll
        for (int nt = 0; nt < 8; nt++) {
            #pragma unroll
            for (int o = 4; o <= 16; o <<= 1) {
                cp0[nt] += __shfl_xor_sync(0xffffffffu, cp0[nt], o);
                cp1[nt] += __shfl_xor_sync(0xffffffffu, cp1[nt], o);
            }
        }
        if (g == 0) {
            #pragma unroll
            for (int nt = 0; nt < 8; nt++) {
                int c = wn * 64 + nt * 8 + t4 * 2;
                sZc[wm][c] = cp0[nt];
                sZc[wm][c + 1] = cp1[nt];
            }
        }
    }
    __syncthreads();

    if (tid < 128) {
        g_partial[(size_t)(ibase + tid) * 32 + bj] = sZr[tid];
        if (!diag) {
            float cs = ((sZc[0][tid] + sZc[1][tid]) + sZc[2][tid]) + sZc[3][tid];
            g_partial[(size_t)(jbase + tid) * 32 + bi] = cs;
        }
    }
}

// ---------------- K3: per-row log-prob (warp per row) + fused final loss ----------------
__global__ void __launch_bounds__(256) k_rowfix(const float* __restrict__ outm,
                                                float* __restrict__ out, int moff) {
    const int wid = threadIdx.x >> 5, lane = threadIdx.x & 31;
    const int i = blockIdx.x * 8 + wid;

    const float4 a = *(const float4*)(g_f + (size_t)i * D + lane * 4);

    auto dot = [&](int j) -> float {
        float4 b = *(const float4*)(g_f + (size_t)j * D + lane * 4);
        float p = a.x * b.x + a.y * b.y + a.z * b.z + a.w * b.w;
        #pragma unroll
        for (int o = 16; o; o >>= 1) p += __shfl_xor_sync(0xffffffffu, p, o);
        return p;
    };

    // corr must match gemm's bf16-level sim so Z - corr is consistent
    auto dotbf = [&](int j) -> float {
        uint2 pa = *(const uint2*)(g_fbf + (size_t)i * 64 + lane * 2);
        uint2 pb = *(const uint2*)(g_fbf + (size_t)j * 64 + lane * 2);
        float ax0 = __uint_as_float(pa.x << 16), ax1 = __uint_as_float(pa.x & 0xffff0000u);
        float ay0 = __uint_as_float(pa.y << 16), ay1 = __uint_as_float(pa.y & 0xffff0000u);
        float bx0 = __uint_as_float(pb.x << 16), bx1 = __uint_as_float(pb.x & 0xffff0000u);
        float by0 = __uint_as_float(pb.y << 16), by1 = __uint_as_float(pb.y & 0xffff0000u);
        float p = ax0 * bx0 + ax1 * bx1 + ay0 * by0 + ay1 * by1;
        #pragma unroll
        for (int o = 16; o; o >>= 1) p += __shfl_xor_sync(0xffffffffu, p, o);
        return p;
    };

    float simpos = (dot(i ^ BHALF) - 1.0f) * INV_T;

    int cnt = g_cnt[i];
    float corr = 0.0f;
    if (cnt <= 64) {
        for (int k = 0; k < cnt; k++) {
            int j = g_sidx[i * 64 + k];
            float m = g_sval[i * 64 + k];
            corr += m * __expf((dotbf(j) - 1.0f) * INV_T);
        }
    } else {
        for (int j = 0; j < N; j++) {
            float m = outm[(size_t)i * N + j];
            if (m > 0.0f) corr += m * __expf((dotbf(j) - 1.0f) * INV_T);
        }
    }

    float zp = g_partial[(size_t)i * 32 + lane];   // one coalesced 128B line per warp
    #pragma unroll
    for (int o = 16; o; o >>= 1) zp += __shfl_xor_sync(0xffffffffu, zp, o);

    if (lane == 0) g_lp[i] = simpos - logf(zp - corr);

    // ---- last-block loss reduction (threadFenceReduction pattern; deterministic order) ----
    __syncthreads();
    __shared__ bool isLast;
    if (threadIdx.x == 0) {
        __threadfence();
        int prev = atomicAdd(&g_done, 1);
        isLast = (prev == (int)gridDim.x - 1);
    }
    __syncthreads();
    if (isLast) {
        __shared__ float sm[8];
        float s = 0.0f;
        #pragma unroll
        for (int k = 0; k < 16; k++) s += g_lp[threadIdx.x + k * 256];
        #pragma unroll
        for (int o = 16; o; o >>= 1) s += __shfl_xor_sync(0xffffffffu, s, o);
        if (lane == 0) sm[wid] = s;
        __syncthreads();
        if (threadIdx.x == 0) {
            float tot = ((sm[0] + sm[1]) + (sm[2] + sm[3])) + ((sm[4] + sm[5]) + (sm[6] + sm[7]));
            float loss = -(tot / 4096.0f);
            for (int q = 0; q < moff; q++) out[q] = loss;
            g_done = 0;   // reset for next graph replay
        }
    }
}

// ---------------- launch ----------------
extern "C" void kernel_launch(void* const* d_in, const int* in_sizes, int n_in,
                              void* d_out, int out_size) {
    int fidx = (in_sizes[0] == N * D) ? 0 : 1;
    const float* feat = (const float*)d_in[fidx];
    const float* attn = (const float*)d_in[1 - fidx];
    float* out = (float*)d_out;

    long long nn = (long long)N * (long long)N;
    int moff = (int)((long long)out_size - nn);
    if (moff < 0) moff = 0;
    float* outm = out + moff;

    k_sparse<<<N, 512>>>(feat, attn, outm);
    k_gemm<<<528, 256>>>();
    k_rowfix<<<512, 256>>>(outm, out, moff);
}